// round 3
// baseline (speedup 1.0000x reference)
#include <cuda_runtime.h>
#include <math.h>
#include <stdint.h>
#include <stddef.h>

// ---------------- problem constants ----------------
#define BB 4096
#define DD 1024
#define TT 768
#define CC 16
#define HH 4
#define HD 256
#define CURVF 0.05f
#define SQC 0.22360679774997896f   /* sqrt(0.05) */
#define EPS8 1e-8f
#define ASINH_MAXF 11.090354888959125f /* asinh(2^15) */

// output layout (flat float32, tuple order):
// logits (B*C) | hyp_loss (1) | oh (B*D) | fh (B*D) | oeu (B*D) | feu (B*D)
#define OFF_LOGITS 0
#define OFF_LOSS   ((size_t)BB*CC)
#define OFF_OH     (OFF_LOSS + 1)
#define OFF_FH     (OFF_OH + (size_t)BB*DD)
#define OFF_OEU    (OFF_FH + (size_t)BB*DD)
#define OFF_FEU    (OFF_OEU + (size_t)BB*DD)

// ---------------- device scratch (static, allocation-free) ----------------
__device__ float g_gf[(size_t)BB*4*DD];          // (B,4,D)
__device__ float g_qkv[(size_t)BB*4*3*DD];       // (B,4,3D)
__device__ float g_attn[(size_t)BB*4*DD];        // attention output (pre out-proj)
__device__ float g_attn2[(size_t)BB*4*DD];       // out-proj output
__device__ float g_OF[(size_t)BB*DD];
__device__ float g_FF[(size_t)BB*DD];
__device__ float g_ohn2[BB];
__device__ float g_fhn2[BB];
__device__ float g_ordpen[BB];
__device__ float g_fampen[BB];
__device__ float g_pp[CC*DD];
__device__ float g_ap[CC*DD];
__device__ float g_pp2[CC];
__device__ float g_pa[CC];
__device__ float g_Bc[CC];
__device__ float g_an[CC];
__device__ float g_kk[CC];

// ---------------- helpers ----------------
__device__ __forceinline__ float blockReduceSum256(float v, float* sm32) {
    int tid = threadIdx.x;
    #pragma unroll
    for (int o = 16; o; o >>= 1) v += __shfl_xor_sync(0xffffffffu, v, o);
    if ((tid & 31) == 0) sm32[tid >> 5] = v;
    __syncthreads();
    float r = 0.f;
    if (tid < 8) r = sm32[tid];
    if (tid < 32) {
        #pragma unroll
        for (int o = 4; o; o >>= 1) r += __shfl_xor_sync(0xffffffffu, r, o);
    }
    if (tid == 0) sm32[0] = r;
    __syncthreads();
    r = sm32[0];
    __syncthreads();
    return r;
}

// ---------------- kernel 1: p_logmap0 rows -> gf (B,4,D) ----------------
__global__ void build_gf_kernel(const float* __restrict__ ohp, const float* __restrict__ fhp,
                                const float* __restrict__ oeu, const float* __restrict__ feu) {
    __shared__ float sm[32];
    int b = blockIdx.x, tid = threadIdx.x;
    #pragma unroll
    for (int r = 0; r < 2; r++) {
        const float* src = (r == 0 ? ohp : fhp) + (size_t)b * DD;
        float4 v = reinterpret_cast<const float4*>(src)[tid];
        float s2 = v.x*v.x + v.y*v.y + v.z*v.z + v.w*v.w;
        float n2 = blockReduceSum256(s2, sm);
        float n = fmaxf(sqrtf(n2), 1e-15f);
        float t = SQC * n;
        float tc = fminf(fmaxf(t, -1.f + 1e-5f), 1.f - 1e-5f);
        float art = 0.5f * (log1pf(tc) - log1pf(-tc));
        float scl = art / (n * SQC);
        float4 o = make_float4(v.x*scl, v.y*scl, v.z*scl, v.w*scl);
        reinterpret_cast<float4*>(g_gf + (size_t)b*4*DD + (size_t)r*DD)[tid] = o;
    }
    float4 a = reinterpret_cast<const float4*>(oeu + (size_t)b*DD)[tid];
    reinterpret_cast<float4*>(g_gf + (size_t)b*4*DD + 2*DD)[tid] = a;
    float4 c = reinterpret_cast<const float4*>(feu + (size_t)b*DD)[tid];
    reinterpret_cast<float4*>(g_gf + (size_t)b*4*DD + 3*DD)[tid] = c;
}

// ---------------- kernel 2: generic NT GEMM  C = A * W^T + bias ----------------
// A: (M,K) row-major; W: (N,K) row-major; C: (M,N) row-major.
// M%128==0, N%128==0, K%16==0 required.
#define GBM 128
#define GBN 128
#define GBK 16
__global__ __launch_bounds__(256)
void gemm_nt_bias(const float* __restrict__ A, const float* __restrict__ W,
                  const float* __restrict__ bias, float* __restrict__ Cm,
                  int M, int N, int K) {
    __shared__ float As[GBK][GBM + 4];
    __shared__ float Bs[GBK][GBN + 4];
    int bm = blockIdx.y * GBM, bn = blockIdx.x * GBN;
    int tid = threadIdx.x;
    int tx = tid & 15, ty = tid >> 4;
    float acc[8][8];
    #pragma unroll
    for (int i = 0; i < 8; i++)
        #pragma unroll
        for (int j = 0; j < 8; j++) acc[i][j] = 0.f;

    for (int k0 = 0; k0 < K; k0 += GBK) {
        #pragma unroll
        for (int it = 0; it < 2; it++) {
            int l = tid + it * 256;           // 0..511
            int row = l >> 2;                 // 0..127
            int kq = (l & 3) << 2;            // 0,4,8,12
            float4 a4 = *reinterpret_cast<const float4*>(A + (size_t)(bm + row) * K + k0 + kq);
            As[kq+0][row] = a4.x; As[kq+1][row] = a4.y; As[kq+2][row] = a4.z; As[kq+3][row] = a4.w;
            float4 b4 = *reinterpret_cast<const float4*>(W + (size_t)(bn + row) * K + k0 + kq);
            Bs[kq+0][row] = b4.x; Bs[kq+1][row] = b4.y; Bs[kq+2][row] = b4.z; Bs[kq+3][row] = b4.w;
        }
        __syncthreads();
        #pragma unroll
        for (int k = 0; k < GBK; k++) {
            float4 a0 = *reinterpret_cast<float4*>(&As[k][ty * 8]);
            float4 a1 = *reinterpret_cast<float4*>(&As[k][ty * 8 + 4]);
            float4 b0 = *reinterpret_cast<float4*>(&Bs[k][tx * 8]);
            float4 b1 = *reinterpret_cast<float4*>(&Bs[k][tx * 8 + 4]);
            float av[8] = {a0.x,a0.y,a0.z,a0.w,a1.x,a1.y,a1.z,a1.w};
            float bv[8] = {b0.x,b0.y,b0.z,b0.w,b1.x,b1.y,b1.z,b1.w};
            #pragma unroll
            for (int i = 0; i < 8; i++)
                #pragma unroll
                for (int j = 0; j < 8; j++)
                    acc[i][j] = fmaf(av[i], bv[j], acc[i][j]);
        }
        __syncthreads();
    }
    #pragma unroll
    for (int i = 0; i < 8; i++) {
        int m = bm + ty * 8 + i;
        #pragma unroll
        for (int j = 0; j < 8; j += 4) {
            int n = bn + tx * 8 + j;
            float4 o;
            o.x = acc[i][j+0] + bias[n+0];
            o.y = acc[i][j+1] + bias[n+1];
            o.z = acc[i][j+2] + bias[n+2];
            o.w = acc[i][j+3] + bias[n+3];
            *reinterpret_cast<float4*>(Cm + (size_t)m * N + n) = o;
        }
    }
}

// ---------------- kernel 3: attention (S=4, per-batch block) ----------------
__global__ __launch_bounds__(256)
void attn_kernel() {
    __shared__ float Ks[4][DD];
    __shared__ float Vs[4][DD];
    __shared__ float Sc[HH][4][4];
    int b = blockIdx.x, tid = threadIdx.x;
    const float* base = g_qkv + (size_t)b * 4 * 3 * DD;
    for (int t = 0; t < 4; t++) {
        for (int i = tid; i < DD; i += 256) {
            Ks[t][i] = base[(size_t)t * 3 * DD + DD + i];
            Vs[t][i] = base[(size_t)t * 3 * DD + 2 * DD + i];
        }
    }
    __syncthreads();
    int warp = tid >> 5, lane = tid & 31;
    #pragma unroll
    for (int d8 = 0; d8 < 8; d8++) {
        int id = warp * 8 + d8;          // 0..63
        int h = id >> 4, tq = (id >> 2) & 3, tk = id & 3;
        const float* qrow = base + (size_t)tq * 3 * DD + h * HD;
        float s = 0.f;
        #pragma unroll
        for (int i = lane; i < HD; i += 32) s += qrow[i] * Ks[tk][h * HD + i];
        #pragma unroll
        for (int o = 16; o; o >>= 1) s += __shfl_xor_sync(0xffffffffu, s, o);
        if (lane == 0) Sc[h][tq][tk] = s * (1.0f / 16.0f);
    }
    __syncthreads();
    if (tid < 16) {
        int h = tid >> 2, tq = tid & 3;
        float m = Sc[h][tq][0];
        #pragma unroll
        for (int k = 1; k < 4; k++) m = fmaxf(m, Sc[h][tq][k]);
        float e[4], se = 0.f;
        #pragma unroll
        for (int k = 0; k < 4; k++) { e[k] = expf(Sc[h][tq][k] - m); se += e[k]; }
        #pragma unroll
        for (int k = 0; k < 4; k++) Sc[h][tq][k] = e[k] / se;
    }
    __syncthreads();
    #pragma unroll
    for (int t = 0; t < 4; t++) {
        for (int i = tid; i < DD; i += 256) {
            int h = i >> 8;
            float a = 0.f;
            #pragma unroll
            for (int tk = 0; tk < 4; tk++) a = fmaf(Sc[h][t][tk], Vs[tk][i], a);
            g_attn[(size_t)b * 4 * DD + (size_t)t * DD + i] = a;
        }
    }
}

// ---------------- kernel 5: residual + LN + split + l_expmap0 ----------------
__global__ void ln_split_kernel(const float* __restrict__ lnw, const float* __restrict__ lnb,
                                float* __restrict__ out) {
    __shared__ float sm[32];
    int row = blockIdx.x;           // b*4 + t
    int b = row >> 2, t = row & 3;
    int tid = threadIdx.x;
    float4 x = reinterpret_cast<const float4*>(g_gf + (size_t)row * DD)[tid];
    float4 a = reinterpret_cast<const float4*>(g_attn2 + (size_t)row * DD)[tid];
    x.x += a.x; x.y += a.y; x.z += a.z; x.w += a.w;
    float s  = x.x + x.y + x.z + x.w;
    float sq = x.x*x.x + x.y*x.y + x.z*x.z + x.w*x.w;
    float sum = blockReduceSum256(s, sm);
    float sumsq = blockReduceSum256(sq, sm);
    float mu = sum * (1.0f / DD);
    float var = sumsq * (1.0f / DD) - mu * mu;
    float rstd = rsqrtf(var + 1e-5f);
    float4 w = reinterpret_cast<const float4*>(lnw)[tid];
    float4 bb = reinterpret_cast<const float4*>(lnb)[tid];
    float4 y;
    y.x = (x.x - mu) * rstd * w.x + bb.x;
    y.y = (x.y - mu) * rstd * w.y + bb.y;
    y.z = (x.z - mu) * rstd * w.z + bb.z;
    y.w = (x.w - mu) * rstd * w.w + bb.w;
    if (t >= 2) {
        float* dst = out + (t == 2 ? OFF_OEU : OFF_FEU) + (size_t)b * DD + (size_t)tid * 4;
        dst[0] = y.x; dst[1] = y.y; dst[2] = y.z; dst[3] = y.w;
    } else {
        float n2 = blockReduceSum256(y.x*y.x + y.y*y.y + y.z*y.z + y.w*y.w, sm);
        float rc = SQC * sqrtf(n2);
        float si = fminf(fmaxf(rc, EPS8), ASINH_MAXF);
        float scl = sinhf(si) / fmaxf(rc, EPS8);
        float* dst = out + (t == 0 ? OFF_OH : OFF_FH) + (size_t)b * DD + (size_t)tid * 4;
        dst[0] = y.x * scl; dst[1] = y.y * scl; dst[2] = y.z * scl; dst[3] = y.w * scl;
        if (tid == 0) {
            float on2 = scl * scl * n2;
            if (t == 0) g_ohn2[b] = on2; else g_fhn2[b] = on2;
        }
    }
}

// ---------------- kernel 7: per-row penalty ----------------
__device__ __forceinline__ float penalty_scalar(float F2, float FY, float yn2) {
    // x = l_expmap0(F); oxy_angle(x,y) - half_aperture(x), relu
    float nF = sqrtf(F2);
    float rc = SQC * nF;
    float si = fminf(fmaxf(rc, EPS8), ASINH_MAXF);
    float s = sinhf(si) / fmaxf(rc, EPS8);
    float x2 = s * s * F2;
    float nx = s * nF;
    float xy = s * FY;
    float xt = sqrtf(1.0f / CURVF + x2);
    float yt = sqrtf(1.0f / CURVF + yn2);
    float cxyl = CURVF * (xy - xt * yt);
    float num = yt + cxyl * xt;
    float den = sqrtf(fmaxf(cxyl * cxyl - 1.0f, EPS8));
    float ai = num / (nx * den + EPS8);
    ai = fminf(fmaxf(ai, -1.f + EPS8), 1.f - EPS8);
    float ang = acosf(ai);
    float asin_in = 0.2f / (nx * SQC + EPS8);
    asin_in = fminf(fmaxf(asin_in, -1.f + EPS8), 1.f - EPS8);
    float ap = asinf(asin_in);
    return fmaxf(ang - ap, 0.f);
}

__global__ void loss_kernel(const int* __restrict__ mask, const float* __restrict__ out) {
    __shared__ float sm[32];
    int b = blockIdx.x, tid = threadIdx.x;
    const float* OF = g_OF + (size_t)b * DD;
    const float* FF = g_FF + (size_t)b * DD;
    const float* fh = out + OFF_FH + (size_t)b * DD;
    const float* oh = out + OFF_OH + (size_t)b * DD;
    float doo = 0.f, doy = 0.f, dff = 0.f, dfy = 0.f;
    for (int i = tid; i < DD; i += 256) {
        float o = OF[i], f = FF[i];
        doo += o * o; doy += o * fh[i];
        dff += f * f; dfy += f * oh[i];
    }
    doo = blockReduceSum256(doo, sm);
    doy = blockReduceSum256(doy, sm);
    dff = blockReduceSum256(dff, sm);
    dfy = blockReduceSum256(dfy, sm);
    if (tid == 0) {
        g_ordpen[b] = penalty_scalar(doo, doy, g_fhn2[b]);
        g_fampen[b] = penalty_scalar(dff, dfy, g_ohn2[b]) * (float)mask[b];
    }
}

// ---------------- kernel 8: deterministic loss reduction ----------------
__global__ void loss_reduce_kernel(const int* __restrict__ mask, float* __restrict__ out) {
    __shared__ float smo[1024];
    __shared__ float smf[1024];
    __shared__ int   smc[1024];
    int tid = threadIdx.x;
    float so = 0.f, sf = 0.f; int c = 0;
    for (int i = tid; i < BB; i += 1024) { so += g_ordpen[i]; sf += g_fampen[i]; c += mask[i]; }
    smo[tid] = so; smf[tid] = sf; smc[tid] = c;
    __syncthreads();
    for (int st = 512; st; st >>= 1) {
        if (tid < st) { smo[tid] += smo[tid + st]; smf[tid] += smf[tid + st]; smc[tid] += smc[tid + st]; }
        __syncthreads();
    }
    if (tid == 0) {
        float ol = smo[0] / (float)BB;
        float cnt = (float)smc[0];
        float fl = (cnt > 0.f) ? smf[0] / fmaxf(cnt, 1.f) : 0.f;
        out[OFF_LOSS] = ol + fl;
    }
}

// ---------------- kernel 9: MLR precompute (per-class scalars) ----------------
__global__ void mlr_prep_kernel(const float* __restrict__ a, const float* __restrict__ p) {
    int warp = threadIdx.x >> 5, lane = threadIdx.x & 31;
    int c = warp; // 16 warps
    const float* pr = p + (size_t)c * DD;
    const float* ar = a + (size_t)c * DD;
    float pn2 = 0.f, pa0 = 0.f, an2 = 0.f;
    for (int i = lane; i < DD; i += 32) {
        float pv = pr[i], av = ar[i];
        pn2 += pv * pv; pa0 += pv * av; an2 += av * av;
    }
    #pragma unroll
    for (int o = 16; o; o >>= 1) {
        pn2 += __shfl_xor_sync(0xffffffffu, pn2, o);
        pa0 += __shfl_xor_sync(0xffffffffu, pa0, o);
        an2 += __shfl_xor_sync(0xffffffffu, an2, o);
    }
    float n = fmaxf(sqrtf(pn2), 1e-15f);
    float t = SQC * n;
    float scl = tanhf(t) / (SQC * n);      // p_expmap0 scale
    float pp2 = scl * scl * pn2;
    float conf = 1.0f - CURVF * pp2;
    for (int i = lane; i < DD; i += 32) {
        g_pp[(size_t)c * DD + i] = pr[i] * scl;
        g_ap[(size_t)c * DD + i] = ar[i] * conf;
    }
    if (lane == 0) {
        float pa = conf * scl * pa0;       // p_p . a_p
        float an = fabsf(conf) * sqrtf(an2);
        float lam = 2.0f / (1.0f - CURVF * pp2);
        g_pp2[c] = pp2; g_pa[c] = pa; g_Bc[c] = conf; g_an[c] = an;
        g_kk[c] = lam * an / SQC;
    }
}

// ---------------- kernel 10: MLR logits (fused hyp_pt + mobius closed form) ----------------
__global__ __launch_bounds__(512)
void mlr_kernel(float* __restrict__ out) {
    __shared__ float xs[DD];
    int b = blockIdx.x, tid = threadIdx.x;
    const float* oh = out + OFF_OH + (size_t)b * DD;
    for (int i = tid; i < DD; i += 512) xs[i] = oh[i];
    __syncthreads();
    float ohn2 = g_ohn2[b];
    // composed scale: l_logmap0 -> p_expmap0 -> p_project (all norm-only rescales)
    float n0 = sqrtf(fmaxf(ohn2, 0.f));
    float rc = SQC * n0;
    float s1 = asinhf(rc) / fmaxf(rc, EPS8);
    float nU = s1 * n0;
    float nUc = fmaxf(nU, 1e-15f);
    float s2 = tanhf(SQC * nUc) / (SQC * nUc);
    float nV = s2 * nU;
    float maxn = 0.996f / SQC;
    float nVc = fmaxf(nV, 1e-15f);
    float s3 = (nVc > maxn) ? (maxn / nVc) : 1.0f;
    float sG = s1 * s2 * s3;

    int c = tid >> 5, lane = tid & 31;   // 16 warps = 16 classes
    const float* pp = g_pp + (size_t)c * DD;
    const float* ap = g_ap + (size_t)c * DD;
    float dp = 0.f, da = 0.f;
    for (int i = lane; i < DD; i += 32) {
        float xv = xs[i];
        dp += xv * pp[i];
        da += xv * ap[i];
    }
    #pragma unroll
    for (int o = 16; o; o >>= 1) {
        dp += __shfl_xor_sync(0xffffffffu, dp, o);
        da += __shfl_xor_sync(0xffffffffu, da, o);
    }
    if (lane == 0) {
        float xy = -sG * dp;                // (-p_p).x
        float xa =  sG * da;                // x.a_p
        float y2 = sG * sG * ohn2;          // |x|^2
        float x2 = g_pp2[c];                // |p_p|^2
        float Bc = g_Bc[c];
        float A = 1.0f + 2.0f * CURVF * xy + CURVF * y2;
        float den = 1.0f + 2.0f * CURVF * xy + CURVF * CURVF * x2 * y2;
        float denp = den + 1e-5f;
        float mdot = (-A * g_pa[c] + Bc * xa) / denp;          // mob . a_p
        float num = 2.0f * SQC * mdot;
        float mob2 = (A * A * x2 + 2.0f * A * Bc * xy + Bc * Bc * y2) / (denp * denp);
        float dml = g_an[c] * (1.0f - CURVF * mob2);
        out[(size_t)b * CC + c] = g_kk[c] * asinhf(num / dml);
    }
}

// ---------------- host ----------------
extern "C" void kernel_launch(void* const* d_in, const int* in_sizes, int n_in,
                              void* d_out, int out_size) {
    const float* order_hyp  = (const float*)d_in[0];
    const float* family_hyp = (const float*)d_in[1];
    const float* order_euc  = (const float*)d_in[2];
    const float* family_euc = (const float*)d_in[3];
    const float* order_in   = (const float*)d_in[4];
    const float* family_in  = (const float*)d_in[5];
    const int*   mask       = (const int*)d_in[6];
    const float* in_proj_w  = (const float*)d_in[7];
    const float* in_proj_b  = (const float*)d_in[8];
    const float* out_proj_w = (const float*)d_in[9];
    const float* out_proj_b = (const float*)d_in[10];
    const float* ln_w       = (const float*)d_in[11];
    const float* ln_b       = (const float*)d_in[12];
    const float* to_w       = (const float*)d_in[13];
    const float* to_b       = (const float*)d_in[14];
    const float* tf_w       = (const float*)d_in[15];
    const float* tf_b       = (const float*)d_in[16];
    const float* mlr_a      = (const float*)d_in[17];
    const float* mlr_p      = (const float*)d_in[18];
    float* out = (float*)d_out;

    float *gf, *qkv, *attn, *attn2, *OFp, *FFp;
    cudaGetSymbolAddress((void**)&gf,    g_gf);
    cudaGetSymbolAddress((void**)&qkv,   g_qkv);
    cudaGetSymbolAddress((void**)&attn,  g_attn);
    cudaGetSymbolAddress((void**)&attn2, g_attn2);
    cudaGetSymbolAddress((void**)&OFp,   g_OF);
    cudaGetSymbolAddress((void**)&FFp,   g_FF);

    // 1. hyperbolic logmap + stack -> gf
    build_gf_kernel<<<BB, 256>>>(order_hyp, family_hyp, order_euc, family_euc);

    // 2. QKV GEMM: (16384,1024) x (3072,1024)^T
    gemm_nt_bias<<<dim3((3 * DD) / GBN, (BB * 4) / GBM), 256>>>(
        gf, in_proj_w, in_proj_b, qkv, BB * 4, 3 * DD, DD);

    // 3. attention
    attn_kernel<<<BB, 256>>>();

    // 4. out-proj GEMM
    gemm_nt_bias<<<dim3(DD / GBN, (BB * 4) / GBM), 256>>>(
        attn, out_proj_w, out_proj_b, attn2, BB * 4, DD, DD);

    // 5. residual + LN + split + l_expmap0
    ln_split_kernel<<<BB * 4, 256>>>(ln_w, ln_b, out);

    // 6. feature GEMMs: (4096,768) x (1024,768)^T
    gemm_nt_bias<<<dim3(DD / GBN, BB / GBM), 256>>>(order_in,  to_w, to_b, OFp, BB, DD, TT);
    gemm_nt_bias<<<dim3(DD / GBN, BB / GBM), 256>>>(family_in, tf_w, tf_b, FFp, BB, DD, TT);

    // 7-8. loss
    loss_kernel<<<BB, 256>>>(mask, out);
    loss_reduce_kernel<<<1, 1024>>>(mask, out);

    // 9-10. MLR logits
    mlr_prep_kernel<<<1, 512>>>(mlr_a, mlr_p);
    mlr_kernel<<<BB, 512>>>(out);

    (void)in_sizes; (void)n_in; (void)out_size;
}

// round 7
// speedup vs baseline: 2.5959x; 2.5959x over previous
#include <cuda_runtime.h>
#include <cuda_bf16.h>
#include <math.h>
#include <stdint.h>
#include <stddef.h>

// ---------------- problem constants ----------------
#define BB 4096
#define DD 1024
#define TT 768
#define CC 16
#define HH 4
#define HD 256
#define CURVF 0.05f
#define SQC 0.22360679774997896f   /* sqrt(0.05) */
#define EPS8 1e-8f
#define ASINH_MAXF 11.090354888959125f /* asinh(2^15) */

// output layout (flat float32, tuple order):
// logits (B*C) | hyp_loss (1) | oh (B*D) | fh (B*D) | oeu (B*D) | feu (B*D)
#define OFF_LOGITS 0
#define OFF_LOSS   ((size_t)BB*CC)
#define OFF_OH     (OFF_LOSS + 1)
#define OFF_FH     (OFF_OH + (size_t)BB*DD)
#define OFF_OEU    (OFF_FH + (size_t)BB*DD)
#define OFF_FEU    (OFF_OEU + (size_t)BB*DD)

// ---------------- device scratch (static, allocation-free) ----------------
__device__ float g_gf[(size_t)BB*4*DD];          // (B,4,D)
__device__ float g_qkv[(size_t)BB*4*3*DD];       // (B,4,3D)
__device__ float g_attn[(size_t)BB*4*DD];        // attention output (pre out-proj)
__device__ float g_attn2[(size_t)BB*4*DD];       // out-proj output
__device__ float g_OF[(size_t)BB*DD];
__device__ float g_FF[(size_t)BB*DD];
__device__ float g_ohn2[BB];
__device__ float g_fhn2[BB];
__device__ float g_ordpen[BB];
__device__ float g_fampen[BB];
__device__ float g_pp[CC*DD];
__device__ float g_ap[CC*DD];
__device__ float g_pp2[CC];
__device__ float g_pa[CC];
__device__ float g_Bc[CC];
__device__ float g_an[CC];
__device__ float g_kk[CC];
// bf16 split scratch
__device__ __nv_bfloat16 g_ah[(size_t)BB*4*DD];
__device__ __nv_bfloat16 g_al[(size_t)BB*4*DD];
__device__ __nv_bfloat16 g_wh[(size_t)3*DD*DD];
__device__ __nv_bfloat16 g_wl[(size_t)3*DD*DD];

// ---------------- PTX helpers (baseline sm_103 ISA only: mma.sync/ldmatrix/cp.async) ----------------
__device__ __forceinline__ uint32_t smem_u32(const void* p) {
    uint32_t a;
    asm("{ .reg .u64 t; cvta.to.shared.u64 t, %1; cvt.u32.u64 %0, t; }" : "=r"(a) : "l"(p));
    return a;
}
#define SWZ(o) ((uint32_t)(o) ^ ((((uint32_t)(o)) >> 3) & 0x70u))
#define CP_ASYNC16(dst, src) \
    asm volatile("cp.async.cg.shared.global [%0], [%1], 16;" :: "r"(dst), "l"(src))
#define CP_COMMIT() asm volatile("cp.async.commit_group;" ::: "memory")
#define CP_WAIT1()  asm volatile("cp.async.wait_group 1;" ::: "memory")
#define CP_WAIT0()  asm volatile("cp.async.wait_group 0;" ::: "memory")
#define LDMX4(r0, r1, r2, r3, a) \
    asm volatile("ldmatrix.sync.aligned.m8n8.x4.shared.b16 {%0,%1,%2,%3}, [%4];" \
                 : "=r"(r0), "=r"(r1), "=r"(r2), "=r"(r3) : "r"(a))
#define LDMX2(r0, r1, a) \
    asm volatile("ldmatrix.sync.aligned.m8n8.x2.shared.b16 {%0,%1}, [%2];" \
                 : "=r"(r0), "=r"(r1) : "r"(a))
#define MMA16816(d, a0, a1, a2, a3, b0, b1) \
    asm volatile("mma.sync.aligned.m16n8k16.row.col.f32.bf16.bf16.f32 " \
                 "{%0,%1,%2,%3}, {%4,%5,%6,%7}, {%8,%9}, {%0,%1,%2,%3};" \
                 : "+f"((d)[0]), "+f"((d)[1]), "+f"((d)[2]), "+f"((d)[3]) \
                 : "r"(a0), "r"(a1), "r"(a2), "r"(a3), "r"(b0), "r"(b1))

// ---------------- helpers ----------------
__device__ __forceinline__ float blockReduceSum256(float v, float* sm32) {
    int tid = threadIdx.x;
    #pragma unroll
    for (int o = 16; o; o >>= 1) v += __shfl_xor_sync(0xffffffffu, v, o);
    if ((tid & 31) == 0) sm32[tid >> 5] = v;
    __syncthreads();
    float r = 0.f;
    if (tid < 8) r = sm32[tid];
    if (tid < 32) {
        #pragma unroll
        for (int o = 4; o; o >>= 1) r += __shfl_xor_sync(0xffffffffu, r, o);
    }
    if (tid == 0) sm32[0] = r;
    __syncthreads();
    r = sm32[0];
    __syncthreads();
    return r;
}

// ---------------- kernel 0: fp32 -> bf16 hi/lo split ----------------
__global__ void split_bf16(const float4* __restrict__ x, uint2* __restrict__ hi,
                           uint2* __restrict__ lo, int n4) {
    int i = blockIdx.x * 256 + threadIdx.x;
    if (i >= n4) return;
    float4 v = x[i];
    __nv_bfloat16 h0 = __float2bfloat16_rn(v.x), h1 = __float2bfloat16_rn(v.y),
                  h2 = __float2bfloat16_rn(v.z), h3 = __float2bfloat16_rn(v.w);
    __nv_bfloat16 l0 = __float2bfloat16_rn(v.x - __bfloat162float(h0));
    __nv_bfloat16 l1 = __float2bfloat16_rn(v.y - __bfloat162float(h1));
    __nv_bfloat16 l2 = __float2bfloat16_rn(v.z - __bfloat162float(h2));
    __nv_bfloat16 l3 = __float2bfloat16_rn(v.w - __bfloat162float(h3));
    uint2 H, L;
    H.x = ((uint32_t)__bfloat16_as_ushort(h1) << 16) | __bfloat16_as_ushort(h0);
    H.y = ((uint32_t)__bfloat16_as_ushort(h3) << 16) | __bfloat16_as_ushort(h2);
    L.x = ((uint32_t)__bfloat16_as_ushort(l1) << 16) | __bfloat16_as_ushort(l0);
    L.y = ((uint32_t)__bfloat16_as_ushort(l3) << 16) | __bfloat16_as_ushort(l2);
    hi[i] = H;
    lo[i] = L;
}

// ---------------- kernel 1: p_logmap0 rows -> gf (B,4,D) ----------------
__global__ void build_gf_kernel(const float* __restrict__ ohp, const float* __restrict__ fhp,
                                const float* __restrict__ oeu, const float* __restrict__ feu) {
    __shared__ float sm[32];
    int b = blockIdx.x, tid = threadIdx.x;
    #pragma unroll
    for (int r = 0; r < 2; r++) {
        const float* src = (r == 0 ? ohp : fhp) + (size_t)b * DD;
        float4 v = reinterpret_cast<const float4*>(src)[tid];
        float s2 = v.x*v.x + v.y*v.y + v.z*v.z + v.w*v.w;
        float n2 = blockReduceSum256(s2, sm);
        float n = fmaxf(sqrtf(n2), 1e-15f);
        float t = SQC * n;
        float tc = fminf(fmaxf(t, -1.f + 1e-5f), 1.f - 1e-5f);
        float art = 0.5f * (log1pf(tc) - log1pf(-tc));
        float scl = art / (n * SQC);
        float4 o = make_float4(v.x*scl, v.y*scl, v.z*scl, v.w*scl);
        reinterpret_cast<float4*>(g_gf + (size_t)b*4*DD + (size_t)r*DD)[tid] = o;
    }
    float4 a = reinterpret_cast<const float4*>(oeu + (size_t)b*DD)[tid];
    reinterpret_cast<float4*>(g_gf + (size_t)b*4*DD + 2*DD)[tid] = a;
    float4 c = reinterpret_cast<const float4*>(feu + (size_t)b*DD)[tid];
    reinterpret_cast<float4*>(g_gf + (size_t)b*4*DD + 3*DD)[tid] = c;
}

// ---------------- kernel 2: mma.sync split-bf16 NT GEMM ----------------
// C(M,N) = A(M,K)*W(N,K)^T + bias; A/W given as bf16 hi/lo splits.
// M%128==0, N%128==0, K%64==0.
#define TCBM 128
#define TCBN 128
#define TCBK 64
#define TILE_B 16384                  /* 128 rows x 128B */
#define STAGE_B (4*TILE_B)            /* Ah, Al, Bh, Bl */
#define GEMM_DYN_SMEM (2*STAGE_B)     /* 131072 */

__global__ __launch_bounds__(256, 1)
void gemm_mma(const __nv_bfloat16* __restrict__ Ahi, const __nv_bfloat16* __restrict__ Alo,
              const __nv_bfloat16* __restrict__ Whi, const __nv_bfloat16* __restrict__ Wlo,
              const float* __restrict__ bias, float* __restrict__ Cm,
              int M, int N, int K) {
    extern __shared__ char smem[];
    uint32_t sb = smem_u32(smem);
    int tid = threadIdx.x, wid = tid >> 5, lane = tid & 31;
    int warp_m = wid >> 2, warp_n = wid & 3;      // 2 x 4 warps, warp tile 64x32
    int bm = blockIdx.y * TCBM, bn = blockIdx.x * TCBN;

    float acc[4][4][4];
    #pragma unroll
    for (int i = 0; i < 4; i++)
        #pragma unroll
        for (int j = 0; j < 4; j++)
            #pragma unroll
            for (int r = 0; r < 4; r++) acc[i][j][r] = 0.f;

    const int NC = K / TCBK;
    // per-thread load slots: 4 x (row, 16B-seg) covering 128x8 segs
    int lrow[4], lseg[4];
    #pragma unroll
    for (int it = 0; it < 4; it++) {
        int slot = tid + it * 256;
        lrow[it] = slot >> 3;
        lseg[it] = slot & 7;
    }

    // prefetch chunk 0 into stage 0
    {
        uint32_t st = sb;
        #pragma unroll
        for (int it = 0; it < 4; it++) {
            uint32_t sw = SWZ(lrow[it] * 128 + lseg[it] * 16);
            size_t ga = (size_t)(bm + lrow[it]) * K + lseg[it] * 8;
            size_t gb = (size_t)(bn + lrow[it]) * K + lseg[it] * 8;
            CP_ASYNC16(st + 0 * TILE_B + sw, Ahi + ga);
            CP_ASYNC16(st + 1 * TILE_B + sw, Alo + ga);
            CP_ASYNC16(st + 2 * TILE_B + sw, Whi + gb);
            CP_ASYNC16(st + 3 * TILE_B + sw, Wlo + gb);
        }
        CP_COMMIT();
    }

    for (int i = 0; i < NC; i++) {
        if (i + 1 < NC) {
            uint32_t st = sb + ((i + 1) & 1) * STAGE_B;
            int k0 = (i + 1) * TCBK;
            #pragma unroll
            for (int it = 0; it < 4; it++) {
                uint32_t sw = SWZ(lrow[it] * 128 + lseg[it] * 16);
                size_t ga = (size_t)(bm + lrow[it]) * K + k0 + lseg[it] * 8;
                size_t gb = (size_t)(bn + lrow[it]) * K + k0 + lseg[it] * 8;
                CP_ASYNC16(st + 0 * TILE_B + sw, Ahi + ga);
                CP_ASYNC16(st + 1 * TILE_B + sw, Alo + ga);
                CP_ASYNC16(st + 2 * TILE_B + sw, Whi + gb);
                CP_ASYNC16(st + 3 * TILE_B + sw, Wlo + gb);
            }
            CP_COMMIT();
            CP_WAIT1();
        } else {
            CP_WAIT0();
        }
        __syncthreads();

        uint32_t st = sb + (i & 1) * STAGE_B;
        #pragma unroll
        for (int ks = 0; ks < 4; ks++) {
            // A fragments (hi, lo): 4 m-tiles x 4 regs each
            uint32_t ah[4][4], al[4][4];
            int arow = warp_m * 64 + (lane & 15);
            int akel = ks * 16 + ((lane >> 4) << 3);
            #pragma unroll
            for (int mt = 0; mt < 4; mt++) {
                uint32_t off = SWZ((arow + mt * 16) * 128 + akel * 2);
                LDMX4(ah[mt][0], ah[mt][1], ah[mt][2], ah[mt][3], st + 0 * TILE_B + off);
                LDMX4(al[mt][0], al[mt][1], al[mt][2], al[mt][3], st + 1 * TILE_B + off);
            }
            // B fragments (hi, lo): 4 n-tiles x 2 regs each
            uint32_t bh[4][2], bl[4][2];
            int brow = warp_n * 32 + (lane & 7);
            int bkel = ks * 16 + (((lane >> 3) & 1) << 3);
            #pragma unroll
            for (int nt = 0; nt < 4; nt++) {
                uint32_t off = SWZ((brow + nt * 8) * 128 + bkel * 2);
                LDMX2(bh[nt][0], bh[nt][1], st + 2 * TILE_B + off);
                LDMX2(bl[nt][0], bl[nt][1], st + 3 * TILE_B + off);
            }
            #pragma unroll
            for (int mt = 0; mt < 4; mt++) {
                #pragma unroll
                for (int nt = 0; nt < 4; nt++) {
                    MMA16816(acc[mt][nt], ah[mt][0], ah[mt][1], ah[mt][2], ah[mt][3],
                             bh[nt][0], bh[nt][1]);
                    MMA16816(acc[mt][nt], ah[mt][0], ah[mt][1], ah[mt][2], ah[mt][3],
                             bl[nt][0], bl[nt][1]);
                    MMA16816(acc[mt][nt], al[mt][0], al[mt][1], al[mt][2], al[mt][3],
                             bh[nt][0], bh[nt][1]);
                }
            }
        }
        __syncthreads();
    }

    // epilogue: bias + store (float2 per fragment half)
    #pragma unroll
    for (int mt = 0; mt < 4; mt++) {
        int m = bm + warp_m * 64 + mt * 16 + (lane >> 2);
        #pragma unroll
        for (int nt = 0; nt < 4; nt++) {
            int n = bn + warp_n * 32 + nt * 8 + (lane & 3) * 2;
            float2 b01 = *reinterpret_cast<const float2*>(bias + n);
            float2 o0 = make_float2(acc[mt][nt][0] + b01.x, acc[mt][nt][1] + b01.y);
            float2 o1 = make_float2(acc[mt][nt][2] + b01.x, acc[mt][nt][3] + b01.y);
            *reinterpret_cast<float2*>(Cm + (size_t)m * N + n) = o0;
            *reinterpret_cast<float2*>(Cm + (size_t)(m + 8) * N + n) = o1;
        }
    }
}

// ---------------- kernel 3: attention (S=4, per-batch block) ----------------
__global__ __launch_bounds__(256)
void attn_kernel() {
    __shared__ float Ks[4][DD];
    __shared__ float Vs[4][DD];
    __shared__ float Sc[HH][4][4];
    int b = blockIdx.x, tid = threadIdx.x;
    const float* base = g_qkv + (size_t)b * 4 * 3 * DD;
    for (int t = 0; t < 4; t++) {
        for (int i = tid; i < DD; i += 256) {
            Ks[t][i] = base[(size_t)t * 3 * DD + DD + i];
            Vs[t][i] = base[(size_t)t * 3 * DD + 2 * DD + i];
        }
    }
    __syncthreads();
    int warp = tid >> 5, lane = tid & 31;
    #pragma unroll
    for (int d8 = 0; d8 < 8; d8++) {
        int id = warp * 8 + d8;          // 0..63
        int h = id >> 4, tq = (id >> 2) & 3, tk = id & 3;
        const float* qrow = base + (size_t)tq * 3 * DD + h * HD;
        float s = 0.f;
        #pragma unroll
        for (int i = lane; i < HD; i += 32) s += qrow[i] * Ks[tk][h * HD + i];
        #pragma unroll
        for (int o = 16; o; o >>= 1) s += __shfl_xor_sync(0xffffffffu, s, o);
        if (lane == 0) Sc[h][tq][tk] = s * (1.0f / 16.0f);
    }
    __syncthreads();
    if (tid < 16) {
        int h = tid >> 2, tq = tid & 3;
        float m = Sc[h][tq][0];
        #pragma unroll
        for (int k = 1; k < 4; k++) m = fmaxf(m, Sc[h][tq][k]);
        float e[4], se = 0.f;
        #pragma unroll
        for (int k = 0; k < 4; k++) { e[k] = expf(Sc[h][tq][k] - m); se += e[k]; }
        #pragma unroll
        for (int k = 0; k < 4; k++) Sc[h][tq][k] = e[k] / se;
    }
    __syncthreads();
    #pragma unroll
    for (int t = 0; t < 4; t++) {
        for (int i = tid; i < DD; i += 256) {
            int h = i >> 8;
            float a = 0.f;
            #pragma unroll
            for (int tk = 0; tk < 4; tk++) a = fmaf(Sc[h][t][tk], Vs[tk][i], a);
            g_attn[(size_t)b * 4 * DD + (size_t)t * DD + i] = a;
        }
    }
}

// ---------------- kernel 5: residual + LN + split + l_expmap0 ----------------
__global__ void ln_split_kernel(const float* __restrict__ lnw, const float* __restrict__ lnb,
                                float* __restrict__ out) {
    __shared__ float sm[32];
    int row = blockIdx.x;           // b*4 + t
    int b = row >> 2, t = row & 3;
    int tid = threadIdx.x;
    float4 x = reinterpret_cast<const float4*>(g_gf + (size_t)row * DD)[tid];
    float4 a = reinterpret_cast<const float4*>(g_attn2 + (size_t)row * DD)[tid];
    x.x += a.x; x.y += a.y; x.z += a.z; x.w += a.w;
    float s  = x.x + x.y + x.z + x.w;
    float sq = x.x*x.x + x.y*x.y + x.z*x.z + x.w*x.w;
    float sum = blockReduceSum256(s, sm);
    float sumsq = blockReduceSum256(sq, sm);
    float mu = sum * (1.0f / DD);
    float var = sumsq * (1.0f / DD) - mu * mu;
    float rstd = rsqrtf(var + 1e-5f);
    float4 w = reinterpret_cast<const float4*>(lnw)[tid];
    float4 bb = reinterpret_cast<const float4*>(lnb)[tid];
    float4 y;
    y.x = (x.x - mu) * rstd * w.x + bb.x;
    y.y = (x.y - mu) * rstd * w.y + bb.y;
    y.z = (x.z - mu) * rstd * w.z + bb.z;
    y.w = (x.w - mu) * rstd * w.w + bb.w;
    if (t >= 2) {
        float* dst = out + (t == 2 ? OFF_OEU : OFF_FEU) + (size_t)b * DD + (size_t)tid * 4;
        dst[0] = y.x; dst[1] = y.y; dst[2] = y.z; dst[3] = y.w;
    } else {
        float n2 = blockReduceSum256(y.x*y.x + y.y*y.y + y.z*y.z + y.w*y.w, sm);
        float rc = SQC * sqrtf(n2);
        float si = fminf(fmaxf(rc, EPS8), ASINH_MAXF);
        float scl = sinhf(si) / fmaxf(rc, EPS8);
        float* dst = out + (t == 0 ? OFF_OH : OFF_FH) + (size_t)b * DD + (size_t)tid * 4;
        dst[0] = y.x * scl; dst[1] = y.y * scl; dst[2] = y.z * scl; dst[3] = y.w * scl;
        if (tid == 0) {
            float on2 = scl * scl * n2;
            if (t == 0) g_ohn2[b] = on2; else g_fhn2[b] = on2;
        }
    }
}

// ---------------- kernel 7: per-row penalty ----------------
__device__ __forceinline__ float penalty_scalar(float F2, float FY, float yn2) {
    float nF = sqrtf(F2);
    float rc = SQC * nF;
    float si = fminf(fmaxf(rc, EPS8), ASINH_MAXF);
    float s = sinhf(si) / fmaxf(rc, EPS8);
    float x2 = s * s * F2;
    float nx = s * nF;
    float xy = s * FY;
    float xt = sqrtf(1.0f / CURVF + x2);
    float yt = sqrtf(1.0f / CURVF + yn2);
    float cxyl = CURVF * (xy - xt * yt);
    float num = yt + cxyl * xt;
    float den = sqrtf(fmaxf(cxyl * cxyl - 1.0f, EPS8));
    float ai = num / (nx * den + EPS8);
    ai = fminf(fmaxf(ai, -1.f + EPS8), 1.f - EPS8);
    float ang = acosf(ai);
    float asin_in = 0.2f / (nx * SQC + EPS8);
    asin_in = fminf(fmaxf(asin_in, -1.f + EPS8), 1.f - EPS8);
    float ap = asinf(asin_in);
    return fmaxf(ang - ap, 0.f);
}

__global__ void loss_kernel(const int* __restrict__ mask, const float* __restrict__ out) {
    __shared__ float sm[32];
    int b = blockIdx.x, tid = threadIdx.x;
    const float* OF = g_OF + (size_t)b * DD;
    const float* FF = g_FF + (size_t)b * DD;
    const float* fh = out + OFF_FH + (size_t)b * DD;
    const float* oh = out + OFF_OH + (size_t)b * DD;
    float doo = 0.f, doy = 0.f, dff = 0.f, dfy = 0.f;
    for (int i = tid; i < DD; i += 256) {
        float o = OF[i], f = FF[i];
        doo += o * o; doy += o * fh[i];
        dff += f * f; dfy += f * oh[i];
    }
    doo = blockReduceSum256(doo, sm);
    doy = blockReduceSum256(doy, sm);
    dff = blockReduceSum256(dff, sm);
    dfy = blockReduceSum256(dfy, sm);
    if (tid == 0) {
        g_ordpen[b] = penalty_scalar(doo, doy, g_fhn2[b]);
        g_fampen[b] = penalty_scalar(dff, dfy, g_ohn2[b]) * (float)mask[b];
    }
}

// ---------------- kernel 8: deterministic loss reduction ----------------
__global__ void loss_reduce_kernel(const int* __restrict__ mask, float* __restrict__ out) {
    __shared__ float smo[1024];
    __shared__ float smf[1024];
    __shared__ int   smc[1024];
    int tid = threadIdx.x;
    float so = 0.f, sf = 0.f; int c = 0;
    for (int i = tid; i < BB; i += 1024) { so += g_ordpen[i]; sf += g_fampen[i]; c += mask[i]; }
    smo[tid] = so; smf[tid] = sf; smc[tid] = c;
    __syncthreads();
    for (int st = 512; st; st >>= 1) {
        if (tid < st) { smo[tid] += smo[tid + st]; smf[tid] += smf[tid + st]; smc[tid] += smc[tid + st]; }
        __syncthreads();
    }
    if (tid == 0) {
        float ol = smo[0] / (float)BB;
        float cnt = (float)smc[0];
        float fl = (cnt > 0.f) ? smf[0] / fmaxf(cnt, 1.f) : 0.f;
        out[OFF_LOSS] = ol + fl;
    }
}

// ---------------- kernel 9: MLR precompute (per-class scalars) ----------------
__global__ void mlr_prep_kernel(const float* __restrict__ a, const float* __restrict__ p) {
    int warp = threadIdx.x >> 5, lane = threadIdx.x & 31;
    int c = warp; // 16 warps
    const float* pr = p + (size_t)c * DD;
    const float* ar = a + (size_t)c * DD;
    float pn2 = 0.f, pa0 = 0.f, an2 = 0.f;
    for (int i = lane; i < DD; i += 32) {
        float pv = pr[i], av = ar[i];
        pn2 += pv * pv; pa0 += pv * av; an2 += av * av;
    }
    #pragma unroll
    for (int o = 16; o; o >>= 1) {
        pn2 += __shfl_xor_sync(0xffffffffu, pn2, o);
        pa0 += __shfl_xor_sync(0xffffffffu, pa0, o);
        an2 += __shfl_xor_sync(0xffffffffu, an2, o);
    }
    float n = fmaxf(sqrtf(pn2), 1e-15f);
    float t = SQC * n;
    float scl = tanhf(t) / (SQC * n);      // p_expmap0 scale
    float pp2 = scl * scl * pn2;
    float conf = 1.0f - CURVF * pp2;
    for (int i = lane; i < DD; i += 32) {
        g_pp[(size_t)c * DD + i] = pr[i] * scl;
        g_ap[(size_t)c * DD + i] = ar[i] * conf;
    }
    if (lane == 0) {
        float pa = conf * scl * pa0;       // p_p . a_p
        float an = fabsf(conf) * sqrtf(an2);
        float lam = 2.0f / (1.0f - CURVF * pp2);
        g_pp2[c] = pp2; g_pa[c] = pa; g_Bc[c] = conf; g_an[c] = an;
        g_kk[c] = lam * an / SQC;
    }
}

// ---------------- kernel 10: MLR logits ----------------
__global__ __launch_bounds__(512)
void mlr_kernel(float* __restrict__ out) {
    __shared__ float xs[DD];
    int b = blockIdx.x, tid = threadIdx.x;
    const float* oh = out + OFF_OH + (size_t)b * DD;
    for (int i = tid; i < DD; i += 512) xs[i] = oh[i];
    __syncthreads();
    float ohn2 = g_ohn2[b];
    float n0 = sqrtf(fmaxf(ohn2, 0.f));
    float rc = SQC * n0;
    float s1 = asinhf(rc) / fmaxf(rc, EPS8);
    float nU = s1 * n0;
    float nUc = fmaxf(nU, 1e-15f);
    float s2 = tanhf(SQC * nUc) / (SQC * nUc);
    float nV = s2 * nU;
    float maxn = 0.996f / SQC;
    float nVc = fmaxf(nV, 1e-15f);
    float s3 = (nVc > maxn) ? (maxn / nVc) : 1.0f;
    float sG = s1 * s2 * s3;

    int c = tid >> 5, lane = tid & 31;   // 16 warps = 16 classes
    const float* pp = g_pp + (size_t)c * DD;
    const float* ap = g_ap + (size_t)c * DD;
    float dp = 0.f, da = 0.f;
    for (int i = lane; i < DD; i += 32) {
        float xv = xs[i];
        dp += xv * pp[i];
        da += xv * ap[i];
    }
    #pragma unroll
    for (int o = 16; o; o >>= 1) {
        dp += __shfl_xor_sync(0xffffffffu, dp, o);
        da += __shfl_xor_sync(0xffffffffu, da, o);
    }
    if (lane == 0) {
        float xy = -sG * dp;
        float xa =  sG * da;
        float y2 = sG * sG * ohn2;
        float x2 = g_pp2[c];
        float Bc = g_Bc[c];
        float A = 1.0f + 2.0f * CURVF * xy + CURVF * y2;
        float den = 1.0f + 2.0f * CURVF * xy + CURVF * CURVF * x2 * y2;
        float denp = den + 1e-5f;
        float mdot = (-A * g_pa[c] + Bc * xa) / denp;
        float num = 2.0f * SQC * mdot;
        float mob2 = (A * A * x2 + 2.0f * A * Bc * xy + Bc * Bc * y2) / (denp * denp);
        float dml = g_an[c] * (1.0f - CURVF * mob2);
        out[(size_t)b * CC + c] = g_kk[c] * asinhf(num / dml);
    }
}

// ---------------- host ----------------
extern "C" void kernel_launch(void* const* d_in, const int* in_sizes, int n_in,
                              void* d_out, int out_size) {
    const float* order_hyp  = (const float*)d_in[0];
    const float* family_hyp = (const float*)d_in[1];
    const float* order_euc  = (const float*)d_in[2];
    const float* family_euc = (const float*)d_in[3];
    const float* order_in   = (const float*)d_in[4];
    const float* family_in  = (const float*)d_in[5];
    const int*   mask       = (const int*)d_in[6];
    const float* in_proj_w  = (const float*)d_in[7];
    const float* in_proj_b  = (const float*)d_in[8];
    const float* out_proj_w = (const float*)d_in[9];
    const float* out_proj_b = (const float*)d_in[10];
    const float* ln_w       = (const float*)d_in[11];
    const float* ln_b       = (const float*)d_in[12];
    const float* to_w       = (const float*)d_in[13];
    const float* to_b       = (const float*)d_in[14];
    const float* tf_w       = (const float*)d_in[15];
    const float* tf_b       = (const float*)d_in[16];
    const float* mlr_a      = (const float*)d_in[17];
    const float* mlr_p      = (const float*)d_in[18];
    float* out = (float*)d_out;

    float *gf, *qkv, *attn, *attn2, *OFp, *FFp;
    __nv_bfloat16 *ah, *al, *wh, *wl;
    cudaGetSymbolAddress((void**)&gf,    g_gf);
    cudaGetSymbolAddress((void**)&qkv,   g_qkv);
    cudaGetSymbolAddress((void**)&attn,  g_attn);
    cudaGetSymbolAddress((void**)&attn2, g_attn2);
    cudaGetSymbolAddress((void**)&OFp,   g_OF);
    cudaGetSymbolAddress((void**)&FFp,   g_FF);
    cudaGetSymbolAddress((void**)&ah,    g_ah);
    cudaGetSymbolAddress((void**)&al,    g_al);
    cudaGetSymbolAddress((void**)&wh,    g_wh);
    cudaGetSymbolAddress((void**)&wl,    g_wl);

    cudaFuncSetAttribute(gemm_mma, cudaFuncAttributeMaxDynamicSharedMemorySize, GEMM_DYN_SMEM);

    auto split = [&](const float* src, __nv_bfloat16* hi, __nv_bfloat16* lo, size_t n) {
        int n4 = (int)(n / 4);
        split_bf16<<<(n4 + 255) / 256, 256>>>((const float4*)src, (uint2*)hi, (uint2*)lo, n4);
    };

    // 1. hyperbolic logmap + stack -> gf
    build_gf_kernel<<<BB, 256>>>(order_hyp, family_hyp, order_euc, family_euc);

    // 2. QKV GEMM: (16384,1024) x (3072,1024)^T via split-bf16 mma.sync
    split(gf, ah, al, (size_t)BB * 4 * DD);
    split(in_proj_w, wh, wl, (size_t)3 * DD * DD);
    gemm_mma<<<dim3((3 * DD) / TCBN, (BB * 4) / TCBM), 256, GEMM_DYN_SMEM>>>(
        ah, al, wh, wl, in_proj_b, qkv, BB * 4, 3 * DD, DD);

    // 3. attention
    attn_kernel<<<BB, 256>>>();

    // 4. out-proj GEMM
    split(attn, ah, al, (size_t)BB * 4 * DD);
    split(out_proj_w, wh, wl, (size_t)DD * DD);
    gemm_mma<<<dim3(DD / TCBN, (BB * 4) / TCBM), 256, GEMM_DYN_SMEM>>>(
        ah, al, wh, wl, out_proj_b, attn2, BB * 4, DD, DD);

    // 5. residual + LN + split + l_expmap0
    ln_split_kernel<<<BB * 4, 256>>>(ln_w, ln_b, out);

    // 6. feature GEMMs: (4096,768) x (1024,768)^T
    split(order_in, ah, al, (size_t)BB * TT);
    split(to_w, wh, wl, (size_t)DD * TT);
    gemm_mma<<<dim3(DD / TCBN, BB / TCBM), 256, GEMM_DYN_SMEM>>>(
        ah, al, wh, wl, to_b, OFp, BB, DD, TT);
    split(family_in, ah, al, (size_t)BB * TT);
    split(tf_w, wh, wl, (size_t)DD * TT);
    gemm_mma<<<dim3(DD / TCBN, BB / TCBM), 256, GEMM_DYN_SMEM>>>(
        ah, al, wh, wl, tf_b, FFp, BB, DD, TT);

    // 7-8. loss
    loss_kernel<<<BB, 256>>>(mask, out);
    loss_reduce_kernel<<<1, 1024>>>(mask, out);

    // 9-10. MLR logits
    mlr_prep_kernel<<<1, 512>>>(mlr_a, mlr_p);
    mlr_kernel<<<BB, 512>>>(out);

    (void)in_sizes; (void)n_in; (void)out_size;
}

// round 9
// speedup vs baseline: 3.2041x; 1.2343x over previous
#include <cuda_runtime.h>
#include <cuda_fp16.h>
#include <math.h>
#include <stdint.h>
#include <stddef.h>

// ---------------- problem constants ----------------
#define BB 4096
#define DD 1024
#define TT 768
#define CC 16
#define HH 4
#define HD 256
#define CURVF 0.05f
#define SQC 0.22360679774997896f   /* sqrt(0.05) */
#define EPS8 1e-8f
#define ASINH_MAXF 11.090354888959125f /* asinh(2^15) */

// output layout (flat float32, tuple order):
// logits (B*C) | hyp_loss (1) | oh (B*D) | fh (B*D) | oeu (B*D) | feu (B*D)
#define OFF_LOGITS 0
#define OFF_LOSS   ((size_t)BB*CC)
#define OFF_OH     (OFF_LOSS + 1)
#define OFF_FH     (OFF_OH + (size_t)BB*DD)
#define OFF_OEU    (OFF_FH + (size_t)BB*DD)
#define OFF_FEU    (OFF_OEU + (size_t)BB*DD)

// ---------------- device scratch (static, allocation-free) ----------------
__device__ float g_gf[(size_t)BB*4*DD];          // (B,4,D)
__device__ float g_qkv[(size_t)BB*4*3*DD];       // (B,4,3D)
__device__ float g_attn2[(size_t)BB*4*DD];       // out-proj output
__device__ float g_OF[(size_t)BB*DD];
__device__ float g_FF[(size_t)BB*DD];
__device__ float g_ohn2[BB];
__device__ float g_fhn2[BB];
__device__ float g_ordpen[BB];
__device__ float g_fampen[BB];
__device__ float g_pp[CC*DD];
__device__ float g_ap[CC*DD];
__device__ float g_pp2[CC];
__device__ float g_pa[CC];
__device__ float g_Bc[CC];
__device__ float g_an[CC];
__device__ float g_kk[CC];
// fp16 GEMM operand scratch: A hi/lo (up to 16384x1024), W hi (up to 3072x1024)
__device__ __half g_ah[(size_t)BB*4*DD];
__device__ __half g_al[(size_t)BB*4*DD];
__device__ __half g_wh[(size_t)3*DD*DD];

// ---------------- PTX helpers (baseline sm_103 ISA: mma.sync/ldmatrix/cp.async) ----------------
__device__ __forceinline__ uint32_t smem_u32(const void* p) {
    uint32_t a;
    asm("{ .reg .u64 t; cvta.to.shared.u64 t, %1; cvt.u32.u64 %0, t; }" : "=r"(a) : "l"(p));
    return a;
}
#define SWZ(o) ((uint32_t)(o) ^ ((((uint32_t)(o)) >> 3) & 0x70u))
#define CP_ASYNC16(dst, src) \
    asm volatile("cp.async.cg.shared.global [%0], [%1], 16;" :: "r"(dst), "l"(src))
#define CP_COMMIT() asm volatile("cp.async.commit_group;" ::: "memory")
#define CP_WAIT1()  asm volatile("cp.async.wait_group 1;" ::: "memory")
#define CP_WAIT0()  asm volatile("cp.async.wait_group 0;" ::: "memory")
#define LDMX4(r0, r1, r2, r3, a) \
    asm volatile("ldmatrix.sync.aligned.m8n8.x4.shared.b16 {%0,%1,%2,%3}, [%4];" \
                 : "=r"(r0), "=r"(r1), "=r"(r2), "=r"(r3) : "r"(a))
#define LDMX2(r0, r1, a) \
    asm volatile("ldmatrix.sync.aligned.m8n8.x2.shared.b16 {%0,%1}, [%2];" \
                 : "=r"(r0), "=r"(r1) : "r"(a))
#define MMAF16(d, a0, a1, a2, a3, b0, b1) \
    asm volatile("mma.sync.aligned.m16n8k16.row.col.f32.f16.f16.f32 " \
                 "{%0,%1,%2,%3}, {%4,%5,%6,%7}, {%8,%9}, {%0,%1,%2,%3};" \
                 : "+f"((d)[0]), "+f"((d)[1]), "+f"((d)[2]), "+f"((d)[3]) \
                 : "r"(a0), "r"(a1), "r"(a2), "r"(a3), "r"(b0), "r"(b1))

// ---------------- helpers ----------------
__device__ __forceinline__ float blockReduceSum256(float v, float* sm32) {
    int tid = threadIdx.x;
    #pragma unroll
    for (int o = 16; o; o >>= 1) v += __shfl_xor_sync(0xffffffffu, v, o);
    if ((tid & 31) == 0) sm32[tid >> 5] = v;
    __syncthreads();
    float r = 0.f;
    if (tid < 8) r = sm32[tid];
    if (tid < 32) {
        #pragma unroll
        for (int o = 4; o; o >>= 1) r += __shfl_xor_sync(0xffffffffu, r, o);
    }
    if (tid == 0) sm32[0] = r;
    __syncthreads();
    r = sm32[0];
    __syncthreads();
    return r;
}

__device__ __forceinline__ void split4h(float4 v, uint2& H, uint2& L) {
    __half h0 = __float2half_rn(v.x), h1 = __float2half_rn(v.y),
           h2 = __float2half_rn(v.z), h3 = __float2half_rn(v.w);
    __half l0 = __float2half_rn(v.x - __half2float(h0));
    __half l1 = __float2half_rn(v.y - __half2float(h1));
    __half l2 = __float2half_rn(v.z - __half2float(h2));
    __half l3 = __float2half_rn(v.w - __half2float(h3));
    H.x = ((uint32_t)__half_as_ushort(h1) << 16) | __half_as_ushort(h0);
    H.y = ((uint32_t)__half_as_ushort(h3) << 16) | __half_as_ushort(h2);
    L.x = ((uint32_t)__half_as_ushort(l1) << 16) | __half_as_ushort(l0);
    L.y = ((uint32_t)__half_as_ushort(l3) << 16) | __half_as_ushort(l2);
}

// ---------------- fp32 -> fp16 hi/lo split (A operands) ----------------
__global__ void split_f16(const float4* __restrict__ x, uint2* __restrict__ hi,
                          uint2* __restrict__ lo, int n4) {
    int i = blockIdx.x * 256 + threadIdx.x;
    if (i >= n4) return;
    uint2 H, L;
    split4h(x[i], H, L);
    hi[i] = H;
    lo[i] = L;
}

// ---------------- fp32 -> fp16 convert (W operands, hi only) ----------------
__global__ void conv_f16(const float4* __restrict__ x, uint2* __restrict__ h, int n4) {
    int i = blockIdx.x * 256 + threadIdx.x;
    if (i >= n4) return;
    float4 v = x[i];
    __half h0 = __float2half_rn(v.x), h1 = __float2half_rn(v.y),
           h2 = __float2half_rn(v.z), h3 = __float2half_rn(v.w);
    uint2 H;
    H.x = ((uint32_t)__half_as_ushort(h1) << 16) | __half_as_ushort(h0);
    H.y = ((uint32_t)__half_as_ushort(h3) << 16) | __half_as_ushort(h2);
    h[i] = H;
}

// ---------------- kernel 1: p_logmap0 rows -> gf (B,4,D) + fused fp16 split ----------------
__global__ void build_gf_kernel(const float* __restrict__ ohp, const float* __restrict__ fhp,
                                const float* __restrict__ oeu, const float* __restrict__ feu) {
    __shared__ float sm[32];
    int b = blockIdx.x, tid = threadIdx.x;
    #pragma unroll
    for (int r = 0; r < 2; r++) {
        const float* src = (r == 0 ? ohp : fhp) + (size_t)b * DD;
        float4 v = reinterpret_cast<const float4*>(src)[tid];
        float s2 = v.x*v.x + v.y*v.y + v.z*v.z + v.w*v.w;
        float n2 = blockReduceSum256(s2, sm);
        float n = fmaxf(sqrtf(n2), 1e-15f);
        float t = SQC * n;
        float tc = fminf(fmaxf(t, -1.f + 1e-5f), 1.f - 1e-5f);
        float art = 0.5f * (log1pf(tc) - log1pf(-tc));
        float scl = art / (n * SQC);
        float4 o = make_float4(v.x*scl, v.y*scl, v.z*scl, v.w*scl);
        size_t row = (size_t)b * 4 + r;
        reinterpret_cast<float4*>(g_gf + row * DD)[tid] = o;
        uint2 H, L;
        split4h(o, H, L);
        reinterpret_cast<uint2*>(g_ah + row * DD)[tid] = H;
        reinterpret_cast<uint2*>(g_al + row * DD)[tid] = L;
    }
    #pragma unroll
    for (int r = 2; r < 4; r++) {
        const float* src = (r == 2 ? oeu : feu) + (size_t)b * DD;
        float4 v = reinterpret_cast<const float4*>(src)[tid];
        size_t row = (size_t)b * 4 + r;
        reinterpret_cast<float4*>(g_gf + row * DD)[tid] = v;
        uint2 H, L;
        split4h(v, H, L);
        reinterpret_cast<uint2*>(g_ah + row * DD)[tid] = H;
        reinterpret_cast<uint2*>(g_al + row * DD)[tid] = L;
    }
}

// ---------------- kernel 2: mma.sync 2-pass fp16 NT GEMM ----------------
// C(M,N) = A(M,K)*W(N,K)^T + bias;  A as fp16 hi/lo split, W as single fp16.
// M%128==0, N%128==0, K%64==0.
#define TCBM 128
#define TCBN 128
#define TCBK 64
#define TILE_B 16384                  /* 128 rows x 128B */
#define STAGE_B (3*TILE_B)            /* Ah, Al, Wh */
#define GEMM_DYN_SMEM (2*STAGE_B)     /* 98304 */

__global__ __launch_bounds__(512, 1)
void gemm_mma(const __half* __restrict__ Ahi, const __half* __restrict__ Alo,
              const __half* __restrict__ Wh,
              const float* __restrict__ bias, float* __restrict__ Cm,
              int M, int N, int K) {
    extern __shared__ char smem[];
    uint32_t sb = smem_u32(smem);
    int tid = threadIdx.x, wid = tid >> 5, lane = tid & 31;
    int warp_m = wid >> 2, warp_n = wid & 3;   // 4x4 warps, warp tile 32x32
    int bm = blockIdx.y * TCBM, bn = blockIdx.x * TCBN;

    float acc[2][4][4];
    #pragma unroll
    for (int i = 0; i < 2; i++)
        #pragma unroll
        for (int j = 0; j < 4; j++)
            #pragma unroll
            for (int r = 0; r < 4; r++) acc[i][j][r] = 0.f;

    const int NC = K / TCBK;
    // per-thread load map: 2 segs per tile (1024 segs / 512 threads)
    int r0 = tid >> 3, s0 = tid & 7;
    int r1 = (tid + 512) >> 3, s1 = (tid + 512) & 7;
    uint32_t sw0 = SWZ(r0 * 128 + s0 * 16);
    uint32_t sw1 = SWZ(r1 * 128 + s1 * 16);

    // prefetch chunk 0
    {
        uint32_t st = sb;
        size_t ga0 = (size_t)(bm + r0) * K + s0 * 8;
        size_t ga1 = (size_t)(bm + r1) * K + s1 * 8;
        size_t gb0 = (size_t)(bn + r0) * K + s0 * 8;
        size_t gb1 = (size_t)(bn + r1) * K + s1 * 8;
        CP_ASYNC16(st + 0 * TILE_B + sw0, Ahi + ga0);
        CP_ASYNC16(st + 0 * TILE_B + sw1, Ahi + ga1);
        CP_ASYNC16(st + 1 * TILE_B + sw0, Alo + ga0);
        CP_ASYNC16(st + 1 * TILE_B + sw1, Alo + ga1);
        CP_ASYNC16(st + 2 * TILE_B + sw0, Wh + gb0);
        CP_ASYNC16(st + 2 * TILE_B + sw1, Wh + gb1);
        CP_COMMIT();
    }

    for (int i = 0; i < NC; i++) {
        if (i + 1 < NC) {
            uint32_t st = sb + ((i + 1) & 1) * STAGE_B;
            int k0 = (i + 1) * TCBK;
            size_t ga0 = (size_t)(bm + r0) * K + k0 + s0 * 8;
            size_t ga1 = (size_t)(bm + r1) * K + k0 + s1 * 8;
            size_t gb0 = (size_t)(bn + r0) * K + k0 + s0 * 8;
            size_t gb1 = (size_t)(bn + r1) * K + k0 + s1 * 8;
            CP_ASYNC16(st + 0 * TILE_B + sw0, Ahi + ga0);
            CP_ASYNC16(st + 0 * TILE_B + sw1, Ahi + ga1);
            CP_ASYNC16(st + 1 * TILE_B + sw0, Alo + ga0);
            CP_ASYNC16(st + 1 * TILE_B + sw1, Alo + ga1);
            CP_ASYNC16(st + 2 * TILE_B + sw0, Wh + gb0);
            CP_ASYNC16(st + 2 * TILE_B + sw1, Wh + gb1);
            CP_COMMIT();
            CP_WAIT1();
        } else {
            CP_WAIT0();
        }
        __syncthreads();

        uint32_t st = sb + (i & 1) * STAGE_B;
        #pragma unroll
        for (int ks = 0; ks < 4; ks++) {
            uint32_t ah[2][4], al[2][4], bh[4][2];
            int arow = warp_m * 32 + (lane & 15);
            int ak = (ks * 16 + ((lane >> 4) << 3)) * 2;
            #pragma unroll
            for (int mt = 0; mt < 2; mt++) {
                uint32_t off = SWZ((arow + mt * 16) * 128 + ak);
                LDMX4(ah[mt][0], ah[mt][1], ah[mt][2], ah[mt][3], st + 0 * TILE_B + off);
                LDMX4(al[mt][0], al[mt][1], al[mt][2], al[mt][3], st + 1 * TILE_B + off);
            }
            int brow = warp_n * 32 + (lane & 7);
            int bk = (ks * 16 + (((lane >> 3) & 1) << 3)) * 2;
            #pragma unroll
            for (int nt = 0; nt < 4; nt++) {
                uint32_t off = SWZ((brow + nt * 8) * 128 + bk);
                LDMX2(bh[nt][0], bh[nt][1], st + 2 * TILE_B + off);
            }
            #pragma unroll
            for (int mt = 0; mt < 2; mt++) {
                #pragma unroll
                for (int nt = 0; nt < 4; nt++) {
                    MMAF16(acc[mt][nt], ah[mt][0], ah[mt][1], ah[mt][2], ah[mt][3],
                           bh[nt][0], bh[nt][1]);
                    MMAF16(acc[mt][nt], al[mt][0], al[mt][1], al[mt][2], al[mt][3],
                           bh[nt][0], bh[nt][1]);
                }
            }
        }
        __syncthreads();
    }

    // epilogue: bias + store
    #pragma unroll
    for (int mt = 0; mt < 2; mt++) {
        int m = bm + warp_m * 32 + mt * 16 + (lane >> 2);
        #pragma unroll
        for (int nt = 0; nt < 4; nt++) {
            int n = bn + warp_n * 32 + nt * 8 + (lane & 3) * 2;
            float2 b01 = *reinterpret_cast<const float2*>(bias + n);
            float2 o0 = make_float2(acc[mt][nt][0] + b01.x, acc[mt][nt][1] + b01.y);
            float2 o1 = make_float2(acc[mt][nt][2] + b01.x, acc[mt][nt][3] + b01.y);
            *reinterpret_cast<float2*>(Cm + (size_t)m * N + n) = o0;
            *reinterpret_cast<float2*>(Cm + (size_t)(m + 8) * N + n) = o1;
        }
    }
}

// ---------------- kernel 3: attention (S=4, per-batch block), fused fp16 split out ----------------
__global__ __launch_bounds__(256)
void attn_kernel() {
    __shared__ float Ks[4][DD];
    __shared__ float Vs[4][DD];
    __shared__ float Sc[HH][4][4];
    int b = blockIdx.x, tid = threadIdx.x;
    const float* base = g_qkv + (size_t)b * 4 * 3 * DD;
    for (int t = 0; t < 4; t++) {
        for (int i = tid; i < DD; i += 256) {
            Ks[t][i] = base[(size_t)t * 3 * DD + DD + i];
            Vs[t][i] = base[(size_t)t * 3 * DD + 2 * DD + i];
        }
    }
    __syncthreads();
    int warp = tid >> 5, lane = tid & 31;
    #pragma unroll
    for (int d8 = 0; d8 < 8; d8++) {
        int id = warp * 8 + d8;          // 0..63
        int h = id >> 4, tq = (id >> 2) & 3, tk = id & 3;
        const float* qrow = base + (size_t)tq * 3 * DD + h * HD;
        float s = 0.f;
        #pragma unroll
        for (int i = lane; i < HD; i += 32) s += qrow[i] * Ks[tk][h * HD + i];
        #pragma unroll
        for (int o = 16; o; o >>= 1) s += __shfl_xor_sync(0xffffffffu, s, o);
        if (lane == 0) Sc[h][tq][tk] = s * (1.0f / 16.0f);
    }
    __syncthreads();
    if (tid < 16) {
        int h = tid >> 2, tq = tid & 3;
        float m = Sc[h][tq][0];
        #pragma unroll
        for (int k = 1; k < 4; k++) m = fmaxf(m, Sc[h][tq][k]);
        float e[4], se = 0.f;
        #pragma unroll
        for (int k = 0; k < 4; k++) { e[k] = expf(Sc[h][tq][k] - m); se += e[k]; }
        #pragma unroll
        for (int k = 0; k < 4; k++) Sc[h][tq][k] = e[k] / se;
    }
    __syncthreads();
    #pragma unroll
    for (int t = 0; t < 4; t++) {
        for (int i = tid; i < DD; i += 256) {
            int h = i >> 8;
            float a = 0.f;
            #pragma unroll
            for (int tk = 0; tk < 4; tk++) a = fmaf(Sc[h][t][tk], Vs[tk][i], a);
            size_t idx = ((size_t)b * 4 + t) * DD + i;
            __half hh = __float2half_rn(a);
            __half hl = __float2half_rn(a - __half2float(hh));
            g_ah[idx] = hh;
            g_al[idx] = hl;
        }
    }
}

// ---------------- kernel 5: residual + LN + split + l_expmap0 ----------------
__global__ void ln_split_kernel(const float* __restrict__ lnw, const float* __restrict__ lnb,
                                float* __restrict__ out) {
    __shared__ float sm[32];
    int row = blockIdx.x;           // b*4 + t
    int b = row >> 2, t = row & 3;
    int tid = threadIdx.x;
    float4 x = reinterpret_cast<const float4*>(g_gf + (size_t)row * DD)[tid];
    float4 a = reinterpret_cast<const float4*>(g_attn2 + (size_t)row * DD)[tid];
    x.x += a.x; x.y += a.y; x.z += a.z; x.w += a.w;
    float s  = x.x + x.y + x.z + x.w;
    float sq = x.x*x.x + x.y*x.y + x.z*x.z + x.w*x.w;
    float sum = blockReduceSum256(s, sm);
    float sumsq = blockReduceSum256(sq, sm);
    float mu = sum * (1.0f / DD);
    float var = sumsq * (1.0f / DD) - mu * mu;
    float rstd = rsqrtf(var + 1e-5f);
    float4 w = reinterpret_cast<const float4*>(lnw)[tid];
    float4 bb = reinterpret_cast<const float4*>(lnb)[tid];
    float4 y;
    y.x = (x.x - mu) * rstd * w.x + bb.x;
    y.y = (x.y - mu) * rstd * w.y + bb.y;
    y.z = (x.z - mu) * rstd * w.z + bb.z;
    y.w = (x.w - mu) * rstd * w.w + bb.w;
    if (t >= 2) {
        float* dst = out + (t == 2 ? OFF_OEU : OFF_FEU) + (size_t)b * DD + (size_t)tid * 4;
        dst[0] = y.x; dst[1] = y.y; dst[2] = y.z; dst[3] = y.w;
    } else {
        float n2 = blockReduceSum256(y.x*y.x + y.y*y.y + y.z*y.z + y.w*y.w, sm);
        float rc = SQC * sqrtf(n2);
        float si = fminf(fmaxf(rc, EPS8), ASINH_MAXF);
        float scl = sinhf(si) / fmaxf(rc, EPS8);
        float* dst = out + (t == 0 ? OFF_OH : OFF_FH) + (size_t)b * DD + (size_t)tid * 4;
        dst[0] = y.x * scl; dst[1] = y.y * scl; dst[2] = y.z * scl; dst[3] = y.w * scl;
        if (tid == 0) {
            float on2 = scl * scl * n2;
            if (t == 0) g_ohn2[b] = on2; else g_fhn2[b] = on2;
        }
    }
}

// ---------------- kernel 7: per-row penalty ----------------
__device__ __forceinline__ float penalty_scalar(float F2, float FY, float yn2) {
    float nF = sqrtf(F2);
    float rc = SQC * nF;
    float si = fminf(fmaxf(rc, EPS8), ASINH_MAXF);
    float s = sinhf(si) / fmaxf(rc, EPS8);
    float x2 = s * s * F2;
    float nx = s * nF;
    float xy = s * FY;
    float xt = sqrtf(1.0f / CURVF + x2);
    float yt = sqrtf(1.0f / CURVF + yn2);
    float cxyl = CURVF * (xy - xt * yt);
    float num = yt + cxyl * xt;
    float den = sqrtf(fmaxf(cxyl * cxyl - 1.0f, EPS8));
    float ai = num / (nx * den + EPS8);
    ai = fminf(fmaxf(ai, -1.f + EPS8), 1.f - EPS8);
    float ang = acosf(ai);
    float asin_in = 0.2f / (nx * SQC + EPS8);
    asin_in = fminf(fmaxf(asin_in, -1.f + EPS8), 1.f - EPS8);
    float ap = asinf(asin_in);
    return fmaxf(ang - ap, 0.f);
}

__global__ void loss_kernel(const int* __restrict__ mask, const float* __restrict__ out) {
    __shared__ float sm[32];
    int b = blockIdx.x, tid = threadIdx.x;
    const float* OF = g_OF + (size_t)b * DD;
    const float* FF = g_FF + (size_t)b * DD;
    const float* fh = out + OFF_FH + (size_t)b * DD;
    const float* oh = out + OFF_OH + (size_t)b * DD;
    float doo = 0.f, doy = 0.f, dff = 0.f, dfy = 0.f;
    for (int i = tid; i < DD; i += 256) {
        float o = OF[i], f = FF[i];
        doo += o * o; doy += o * fh[i];
        dff += f * f; dfy += f * oh[i];
    }
    doo = blockReduceSum256(doo, sm);
    doy = blockReduceSum256(doy, sm);
    dff = blockReduceSum256(dff, sm);
    dfy = blockReduceSum256(dfy, sm);
    if (tid == 0) {
        g_ordpen[b] = penalty_scalar(doo, doy, g_fhn2[b]);
        g_fampen[b] = penalty_scalar(dff, dfy, g_ohn2[b]) * (float)mask[b];
    }
}

// ---------------- kernel 8: deterministic loss reduction ----------------
__global__ void loss_reduce_kernel(const int* __restrict__ mask, float* __restrict__ out) {
    __shared__ float smo[1024];
    __shared__ float smf[1024];
    __shared__ int   smc[1024];
    int tid = threadIdx.x;
    float so = 0.f, sf = 0.f; int c = 0;
    for (int i = tid; i < BB; i += 1024) { so += g_ordpen[i]; sf += g_fampen[i]; c += mask[i]; }
    smo[tid] = so; smf[tid] = sf; smc[tid] = c;
    __syncthreads();
    for (int st = 512; st; st >>= 1) {
        if (tid < st) { smo[tid] += smo[tid + st]; smf[tid] += smf[tid + st]; smc[tid] += smc[tid + st]; }
        __syncthreads();
    }
    if (tid == 0) {
        float ol = smo[0] / (float)BB;
        float cnt = (float)smc[0];
        float fl = (cnt > 0.f) ? smf[0] / fmaxf(cnt, 1.f) : 0.f;
        out[OFF_LOSS] = ol + fl;
    }
}

// ---------------- kernel 9: MLR precompute (per-class scalars) ----------------
__global__ void mlr_prep_kernel(const float* __restrict__ a, const float* __restrict__ p) {
    int warp = threadIdx.x >> 5, lane = threadIdx.x & 31;
    int c = warp; // 16 warps
    const float* pr = p + (size_t)c * DD;
    const float* ar = a + (size_t)c * DD;
    float pn2 = 0.f, pa0 = 0.f, an2 = 0.f;
    for (int i = lane; i < DD; i += 32) {
        float pv = pr[i], av = ar[i];
        pn2 += pv * pv; pa0 += pv * av; an2 += av * av;
    }
    #pragma unroll
    for (int o = 16; o; o >>= 1) {
        pn2 += __shfl_xor_sync(0xffffffffu, pn2, o);
        pa0 += __shfl_xor_sync(0xffffffffu, pa0, o);
        an2 += __shfl_xor_sync(0xffffffffu, an2, o);
    }
    float n = fmaxf(sqrtf(pn2), 1e-15f);
    float t = SQC * n;
    float scl = tanhf(t) / (SQC * n);      // p_expmap0 scale
    float pp2 = scl * scl * pn2;
    float conf = 1.0f - CURVF * pp2;
    for (int i = lane; i < DD; i += 32) {
        g_pp[(size_t)c * DD + i] = pr[i] * scl;
        g_ap[(size_t)c * DD + i] = ar[i] * conf;
    }
    if (lane == 0) {
        float pa = conf * scl * pa0;       // p_p . a_p
        float an = fabsf(conf) * sqrtf(an2);
        float lam = 2.0f / (1.0f - CURVF * pp2);
        g_pp2[c] = pp2; g_pa[c] = pa; g_Bc[c] = conf; g_an[c] = an;
        g_kk[c] = lam * an / SQC;
    }
}

// ---------------- kernel 10: MLR logits ----------------
__global__ __launch_bounds__(512)
void mlr_kernel(float* __restrict__ out) {
    __shared__ float xs[DD];
    int b = blockIdx.x, tid = threadIdx.x;
    const float* oh = out + OFF_OH + (size_t)b * DD;
    for (int i = tid; i < DD; i += 512) xs[i] = oh[i];
    __syncthreads();
    float ohn2 = g_ohn2[b];
    float n0 = sqrtf(fmaxf(ohn2, 0.f));
    float rc = SQC * n0;
    float s1 = asinhf(rc) / fmaxf(rc, EPS8);
    float nU = s1 * n0;
    float nUc = fmaxf(nU, 1e-15f);
    float s2 = tanhf(SQC * nUc) / (SQC * nUc);
    float nV = s2 * nU;
    float maxn = 0.996f / SQC;
    float nVc = fmaxf(nV, 1e-15f);
    float s3 = (nVc > maxn) ? (maxn / nVc) : 1.0f;
    float sG = s1 * s2 * s3;

    int c = tid >> 5, lane = tid & 31;   // 16 warps = 16 classes
    const float* pp = g_pp + (size_t)c * DD;
    const float* ap = g_ap + (size_t)c * DD;
    float dp = 0.f, da = 0.f;
    for (int i = lane; i < DD; i += 32) {
        float xv = xs[i];
        dp += xv * pp[i];
        da += xv * ap[i];
    }
    #pragma unroll
    for (int o = 16; o; o >>= 1) {
        dp += __shfl_xor_sync(0xffffffffu, dp, o);
        da += __shfl_xor_sync(0xffffffffu, da, o);
    }
    if (lane == 0) {
        float xy = -sG * dp;
        float xa =  sG * da;
        float y2 = sG * sG * ohn2;
        float x2 = g_pp2[c];
        float Bc = g_Bc[c];
        float A = 1.0f + 2.0f * CURVF * xy + CURVF * y2;
        float den = 1.0f + 2.0f * CURVF * xy + CURVF * CURVF * x2 * y2;
        float denp = den + 1e-5f;
        float mdot = (-A * g_pa[c] + Bc * xa) / denp;
        float num = 2.0f * SQC * mdot;
        float mob2 = (A * A * x2 + 2.0f * A * Bc * xy + Bc * Bc * y2) / (denp * denp);
        float dml = g_an[c] * (1.0f - CURVF * mob2);
        out[(size_t)b * CC + c] = g_kk[c] * asinhf(num / dml);
    }
}

// ---------------- host ----------------
extern "C" void kernel_launch(void* const* d_in, const int* in_sizes, int n_in,
                              void* d_out, int out_size) {
    const float* order_hyp  = (const float*)d_in[0];
    const float* family_hyp = (const float*)d_in[1];
    const float* order_euc  = (const float*)d_in[2];
    const float* family_euc = (const float*)d_in[3];
    const float* order_in   = (const float*)d_in[4];
    const float* family_in  = (const float*)d_in[5];
    const int*   mask       = (const int*)d_in[6];
    const float* in_proj_w  = (const float*)d_in[7];
    const float* in_proj_b  = (const float*)d_in[8];
    const float* out_proj_w = (const float*)d_in[9];
    const float* out_proj_b = (const float*)d_in[10];
    const float* ln_w       = (const float*)d_in[11];
    const float* ln_b       = (const float*)d_in[12];
    const float* to_w       = (const float*)d_in[13];
    const float* to_b       = (const float*)d_in[14];
    const float* tf_w       = (const float*)d_in[15];
    const float* tf_b       = (const float*)d_in[16];
    const float* mlr_a      = (const float*)d_in[17];
    const float* mlr_p      = (const float*)d_in[18];
    float* out = (float*)d_out;

    float *qkv, *attn2, *OFp, *FFp;
    __half *ah, *al, *wh;
    cudaGetSymbolAddress((void**)&qkv,   g_qkv);
    cudaGetSymbolAddress((void**)&attn2, g_attn2);
    cudaGetSymbolAddress((void**)&OFp,   g_OF);
    cudaGetSymbolAddress((void**)&FFp,   g_FF);
    cudaGetSymbolAddress((void**)&ah,    g_ah);
    cudaGetSymbolAddress((void**)&al,    g_al);
    cudaGetSymbolAddress((void**)&wh,    g_wh);

    cudaFuncSetAttribute(gemm_mma, cudaFuncAttributeMaxDynamicSharedMemorySize, GEMM_DYN_SMEM);

    auto splitA = [&](const float* src, size_t n) {
        int n4 = (int)(n / 4);
        split_f16<<<(n4 + 255) / 256, 256>>>((const float4*)src, (uint2*)ah, (uint2*)al, n4);
    };
    auto convW = [&](const float* src, size_t n) {
        int n4 = (int)(n / 4);
        conv_f16<<<(n4 + 255) / 256, 256>>>((const float4*)src, (uint2*)wh, n4);
    };

    // 1. hyperbolic logmap + stack -> gf (+ fused fp16 hi/lo split of A)
    build_gf_kernel<<<BB, 256>>>(order_hyp, family_hyp, order_euc, family_euc);

    // 2. QKV GEMM: (16384,1024) x (3072,1024)^T
    convW(in_proj_w, (size_t)3 * DD * DD);
    gemm_mma<<<dim3((3 * DD) / TCBN, (BB * 4) / TCBM), 512, GEMM_DYN_SMEM>>>(
        ah, al, wh, in_proj_b, qkv, BB * 4, 3 * DD, DD);

    // 3. attention (writes fp16 hi/lo A directly)
    attn_kernel<<<BB, 256>>>();

    // 4. out-proj GEMM
    convW(out_proj_w, (size_t)DD * DD);
    gemm_mma<<<dim3(DD / TCBN, (BB * 4) / TCBM), 512, GEMM_DYN_SMEM>>>(
        ah, al, wh, out_proj_b, attn2, BB * 4, DD, DD);

    // 5. residual + LN + split + l_expmap0
    ln_split_kernel<<<BB * 4, 256>>>(ln_w, ln_b, out);

    // 6. feature GEMMs: (4096,768) x (1024,768)^T
    splitA(order_in, (size_t)BB * TT);
    convW(to_w, (size_t)DD * TT);
    gemm_mma<<<dim3(DD / TCBN, BB / TCBM), 512, GEMM_DYN_SMEM>>>(
        ah, al, wh, to_b, OFp, BB, DD, TT);
    splitA(family_in, (size_t)BB * TT);
    convW(tf_w, (size_t)DD * TT);
    gemm_mma<<<dim3(DD / TCBN, BB / TCBM), 512, GEMM_DYN_SMEM>>>(
        ah, al, wh, tf_b, FFp, BB, DD, TT);

    // 7-8. loss
    loss_kernel<<<BB, 256>>>(mask, out);
    loss_reduce_kernel<<<1, 1024>>>(mask, out);

    // 9-10. MLR logits
    mlr_prep_kernel<<<1, 512>>>(mlr_a, mlr_p);
    mlr_kernel<<<BB, 512>>>(out);

    (void)in_sizes; (void)n_in; (void)out_size;
}

// round 10
// speedup vs baseline: 3.2915x; 1.0273x over previous
#include <cuda_runtime.h>
#include <cuda_fp16.h>
#include <math.h>
#include <stdint.h>
#include <stddef.h>

// ---------------- problem constants ----------------
#define BB 4096
#define DD 1024
#define TT 768
#define CC 16
#define HH 4
#define HD 256
#define CURVF 0.05f
#define SQC 0.22360679774997896f   /* sqrt(0.05) */
#define EPS8 1e-8f
#define ASINH_MAXF 11.090354888959125f /* asinh(2^15) */

// output layout (flat float32, tuple order):
// logits (B*C) | hyp_loss (1) | oh (B*D) | fh (B*D) | oeu (B*D) | feu (B*D)
#define OFF_LOGITS 0
#define OFF_LOSS   ((size_t)BB*CC)
#define OFF_OH     (OFF_LOSS + 1)
#define OFF_FH     (OFF_OH + (size_t)BB*DD)
#define OFF_OEU    (OFF_FH + (size_t)BB*DD)
#define OFF_FEU    (OFF_OEU + (size_t)BB*DD)

// ---------------- device scratch (static, allocation-free) ----------------
__device__ float g_gf[(size_t)BB*4*DD];          // (B,4,D)
__device__ __half g_qkvh[(size_t)BB*4*3*DD];     // QKV in fp16
__device__ float g_attn2[(size_t)BB*4*DD];       // out-proj output
__device__ float g_OF[(size_t)BB*DD];
__device__ float g_FF[(size_t)BB*DD];
__device__ float g_ohn2[BB];
__device__ float g_fhn2[BB];
__device__ float g_ordpen[BB];
__device__ float g_fampen[BB];
__device__ float g_pp[CC*DD];
__device__ float g_ap[CC*DD];
__device__ float g_pp2[CC];
__device__ float g_pa[CC];
__device__ float g_Bc[CC];
__device__ float g_an[CC];
__device__ float g_kk[CC];
// fp16 GEMM operand scratch: A hi/lo (up to 16384x1024), W hi (up to 3072x1024)
__device__ __half g_ah[(size_t)BB*4*DD];
__device__ __half g_al[(size_t)BB*4*DD];
__device__ __half g_wh[(size_t)3*DD*DD];

// ---------------- PTX helpers (baseline sm_103 ISA: mma.sync/ldmatrix/cp.async) ----------------
__device__ __forceinline__ uint32_t smem_u32(const void* p) {
    uint32_t a;
    asm("{ .reg .u64 t; cvta.to.shared.u64 t, %1; cvt.u32.u64 %0, t; }" : "=r"(a) : "l"(p));
    return a;
}
#define SWZ(o) ((uint32_t)(o) ^ ((((uint32_t)(o)) >> 3) & 0x70u))
#define CP_ASYNC16(dst, src) \
    asm volatile("cp.async.cg.shared.global [%0], [%1], 16;" :: "r"(dst), "l"(src))
#define CP_COMMIT() asm volatile("cp.async.commit_group;" ::: "memory")
#define CP_WAIT2()  asm volatile("cp.async.wait_group 2;" ::: "memory")
#define CP_WAIT1()  asm volatile("cp.async.wait_group 1;" ::: "memory")
#define CP_WAIT0()  asm volatile("cp.async.wait_group 0;" ::: "memory")
#define LDMX4(r0, r1, r2, r3, a) \
    asm volatile("ldmatrix.sync.aligned.m8n8.x4.shared.b16 {%0,%1,%2,%3}, [%4];" \
                 : "=r"(r0), "=r"(r1), "=r"(r2), "=r"(r3) : "r"(a))
#define LDMX2(r0, r1, a) \
    asm volatile("ldmatrix.sync.aligned.m8n8.x2.shared.b16 {%0,%1}, [%2];" \
                 : "=r"(r0), "=r"(r1) : "r"(a))
#define MMAF16(d, a0, a1, a2, a3, b0, b1) \
    asm volatile("mma.sync.aligned.m16n8k16.row.col.f32.f16.f16.f32 " \
                 "{%0,%1,%2,%3}, {%4,%5,%6,%7}, {%8,%9}, {%0,%1,%2,%3};" \
                 : "+f"((d)[0]), "+f"((d)[1]), "+f"((d)[2]), "+f"((d)[3]) \
                 : "r"(a0), "r"(a1), "r"(a2), "r"(a3), "r"(b0), "r"(b1))

// ---------------- helpers ----------------
__device__ __forceinline__ float blockReduceSum256(float v, float* sm32) {
    int tid = threadIdx.x;
    #pragma unroll
    for (int o = 16; o; o >>= 1) v += __shfl_xor_sync(0xffffffffu, v, o);
    if ((tid & 31) == 0) sm32[tid >> 5] = v;
    __syncthreads();
    float r = 0.f;
    if (tid < 8) r = sm32[tid];
    if (tid < 32) {
        #pragma unroll
        for (int o = 4; o; o >>= 1) r += __shfl_xor_sync(0xffffffffu, r, o);
    }
    if (tid == 0) sm32[0] = r;
    __syncthreads();
    r = sm32[0];
    __syncthreads();
    return r;
}

__device__ __forceinline__ void split4h(float4 v, uint2& H, uint2& L) {
    __half h0 = __float2half_rn(v.x), h1 = __float2half_rn(v.y),
           h2 = __float2half_rn(v.z), h3 = __float2half_rn(v.w);
    __half l0 = __float2half_rn(v.x - __half2float(h0));
    __half l1 = __float2half_rn(v.y - __half2float(h1));
    __half l2 = __float2half_rn(v.z - __half2float(h2));
    __half l3 = __float2half_rn(v.w - __half2float(h3));
    H.x = ((uint32_t)__half_as_ushort(h1) << 16) | __half_as_ushort(h0);
    H.y = ((uint32_t)__half_as_ushort(h3) << 16) | __half_as_ushort(h2);
    L.x = ((uint32_t)__half_as_ushort(l1) << 16) | __half_as_ushort(l0);
    L.y = ((uint32_t)__half_as_ushort(l3) << 16) | __half_as_ushort(l2);
}

// ---------------- fp32 -> fp16 hi/lo split (A operands) ----------------
__global__ void split_f16(const float4* __restrict__ x, uint2* __restrict__ hi,
                          uint2* __restrict__ lo, int n4) {
    int i = blockIdx.x * 256 + threadIdx.x;
    if (i >= n4) return;
    uint2 H, L;
    split4h(x[i], H, L);
    hi[i] = H;
    lo[i] = L;
}

// ---------------- fp32 -> fp16 convert (W operands, hi only) ----------------
__global__ void conv_f16(const float4* __restrict__ x, uint2* __restrict__ h, int n4) {
    int i = blockIdx.x * 256 + threadIdx.x;
    if (i >= n4) return;
    float4 v = x[i];
    __half h0 = __float2half_rn(v.x), h1 = __float2half_rn(v.y),
           h2 = __float2half_rn(v.z), h3 = __float2half_rn(v.w);
    uint2 H;
    H.x = ((uint32_t)__half_as_ushort(h1) << 16) | __half_as_ushort(h0);
    H.y = ((uint32_t)__half_as_ushort(h3) << 16) | __half_as_ushort(h2);
    h[i] = H;
}

// ---------------- kernel 1: p_logmap0 rows -> gf (B,4,D) + fused fp16 split ----------------
__global__ void build_gf_kernel(const float* __restrict__ ohp, const float* __restrict__ fhp,
                                const float* __restrict__ oeu, const float* __restrict__ feu) {
    __shared__ float sm[32];
    int b = blockIdx.x, tid = threadIdx.x;
    #pragma unroll
    for (int r = 0; r < 2; r++) {
        const float* src = (r == 0 ? ohp : fhp) + (size_t)b * DD;
        float4 v = reinterpret_cast<const float4*>(src)[tid];
        float s2 = v.x*v.x + v.y*v.y + v.z*v.z + v.w*v.w;
        float n2 = blockReduceSum256(s2, sm);
        float n = fmaxf(sqrtf(n2), 1e-15f);
        float t = SQC * n;
        float tc = fminf(fmaxf(t, -1.f + 1e-5f), 1.f - 1e-5f);
        float art = 0.5f * (log1pf(tc) - log1pf(-tc));
        float scl = art / (n * SQC);
        float4 o = make_float4(v.x*scl, v.y*scl, v.z*scl, v.w*scl);
        size_t row = (size_t)b * 4 + r;
        reinterpret_cast<float4*>(g_gf + row * DD)[tid] = o;
        uint2 H, L;
        split4h(o, H, L);
        reinterpret_cast<uint2*>(g_ah + row * DD)[tid] = H;
        reinterpret_cast<uint2*>(g_al + row * DD)[tid] = L;
    }
    #pragma unroll
    for (int r = 2; r < 4; r++) {
        const float* src = (r == 2 ? oeu : feu) + (size_t)b * DD;
        float4 v = reinterpret_cast<const float4*>(src)[tid];
        size_t row = (size_t)b * 4 + r;
        reinterpret_cast<float4*>(g_gf + row * DD)[tid] = v;
        uint2 H, L;
        split4h(v, H, L);
        reinterpret_cast<uint2*>(g_ah + row * DD)[tid] = H;
        reinterpret_cast<uint2*>(g_al + row * DD)[tid] = L;
    }
}

// ---------------- kernel 2: mma.sync 2-pass fp16 NT GEMM, 3-stage cp.async ----------------
// C(M,N) = A(M,K)*W(N,K)^T + bias;  A as fp16 hi/lo split, W as single fp16.
// M%128==0, N%128==0, K%64==0.  OutT = float or __half.
#define TCBM 128
#define TCBN 128
#define TCBK 64
#define TILE_B 16384                  /* 128 rows x 128B */
#define STAGE_B (3*TILE_B)            /* Ah, Al, Wh */
#define GEMM_DYN_SMEM (3*STAGE_B)     /* 147456 */

__device__ __forceinline__ void gemm_prefetch(
    uint32_t st, const __half* Ahi, const __half* Alo, const __half* Wh,
    int bm, int bn, int K, int k0,
    int r0, int s0, uint32_t sw0, int r1, int s1, uint32_t sw1) {
    size_t ga0 = (size_t)(bm + r0) * K + k0 + s0 * 8;
    size_t ga1 = (size_t)(bm + r1) * K + k0 + s1 * 8;
    size_t gb0 = (size_t)(bn + r0) * K + k0 + s0 * 8;
    size_t gb1 = (size_t)(bn + r1) * K + k0 + s1 * 8;
    CP_ASYNC16(st + 0 * TILE_B + sw0, Ahi + ga0);
    CP_ASYNC16(st + 0 * TILE_B + sw1, Ahi + ga1);
    CP_ASYNC16(st + 1 * TILE_B + sw0, Alo + ga0);
    CP_ASYNC16(st + 1 * TILE_B + sw1, Alo + ga1);
    CP_ASYNC16(st + 2 * TILE_B + sw0, Wh + gb0);
    CP_ASYNC16(st + 2 * TILE_B + sw1, Wh + gb1);
}

template <typename OutT>
__global__ __launch_bounds__(512, 1)
void gemm_mma(const __half* __restrict__ Ahi, const __half* __restrict__ Alo,
              const __half* __restrict__ Wh,
              const float* __restrict__ bias, OutT* __restrict__ Cm,
              int M, int N, int K) {
    extern __shared__ char smem[];
    uint32_t sb = smem_u32(smem);
    int tid = threadIdx.x, wid = tid >> 5, lane = tid & 31;
    int warp_m = wid >> 2, warp_n = wid & 3;   // 4x4 warps, warp tile 32x32
    int bm = blockIdx.y * TCBM, bn = blockIdx.x * TCBN;

    float acc[2][4][4];
    #pragma unroll
    for (int i = 0; i < 2; i++)
        #pragma unroll
        for (int j = 0; j < 4; j++)
            #pragma unroll
            for (int r = 0; r < 4; r++) acc[i][j][r] = 0.f;

    const int NC = K / TCBK;
    // per-thread load map: 2 segs per tile (1024 segs / 512 threads)
    int r0 = tid >> 3, s0 = tid & 7;
    int r1 = (tid + 512) >> 3, s1 = (tid + 512) & 7;
    uint32_t sw0 = SWZ(r0 * 128 + s0 * 16);
    uint32_t sw1 = SWZ(r1 * 128 + s1 * 16);

    // prefetch chunks 0,1 into stages 0,1
    gemm_prefetch(sb, Ahi, Alo, Wh, bm, bn, K, 0, r0, s0, sw0, r1, s1, sw1);
    CP_COMMIT();
    gemm_prefetch(sb + STAGE_B, Ahi, Alo, Wh, bm, bn, K, TCBK, r0, s0, sw0, r1, s1, sw1);
    CP_COMMIT();

    for (int i = 0; i < NC; i++) {
        int rem = NC - 1 - i;
        if (rem >= 2) {
            gemm_prefetch(sb + (uint32_t)((i + 2) % 3) * STAGE_B, Ahi, Alo, Wh,
                          bm, bn, K, (i + 2) * TCBK, r0, s0, sw0, r1, s1, sw1);
            CP_COMMIT();
            CP_WAIT2();
        } else if (rem == 1) {
            CP_WAIT1();
        } else {
            CP_WAIT0();
        }
        __syncthreads();

        uint32_t st = sb + (uint32_t)(i % 3) * STAGE_B;
        #pragma unroll
        for (int ks = 0; ks < 4; ks++) {
            uint32_t ah[2][4], al[2][4], bh[4][2];
            int arow = warp_m * 32 + (lane & 15);
            int ak = (ks * 16 + ((lane >> 4) << 3)) * 2;
            #pragma unroll
            for (int mt = 0; mt < 2; mt++) {
                uint32_t off = SWZ((arow + mt * 16) * 128 + ak);
                LDMX4(ah[mt][0], ah[mt][1], ah[mt][2], ah[mt][3], st + 0 * TILE_B + off);
                LDMX4(al[mt][0], al[mt][1], al[mt][2], al[mt][3], st + 1 * TILE_B + off);
            }
            int brow = warp_n * 32 + (lane & 7);
            int bk = (ks * 16 + (((lane >> 3) & 1) << 3)) * 2;
            #pragma unroll
            for (int nt = 0; nt < 4; nt++) {
                uint32_t off = SWZ((brow + nt * 8) * 128 + bk);
                LDMX2(bh[nt][0], bh[nt][1], st + 2 * TILE_B + off);
            }
            #pragma unroll
            for (int mt = 0; mt < 2; mt++) {
                #pragma unroll
                for (int nt = 0; nt < 4; nt++) {
                    MMAF16(acc[mt][nt], ah[mt][0], ah[mt][1], ah[mt][2], ah[mt][3],
                           bh[nt][0], bh[nt][1]);
                    MMAF16(acc[mt][nt], al[mt][0], al[mt][1], al[mt][2], al[mt][3],
                           bh[nt][0], bh[nt][1]);
                }
            }
        }
        __syncthreads();
    }

    // epilogue: bias + store
    #pragma unroll
    for (int mt = 0; mt < 2; mt++) {
        int m = bm + warp_m * 32 + mt * 16 + (lane >> 2);
        #pragma unroll
        for (int nt = 0; nt < 4; nt++) {
            int n = bn + warp_n * 32 + nt * 8 + (lane & 3) * 2;
            float2 b01 = *reinterpret_cast<const float2*>(bias + n);
            float v00 = acc[mt][nt][0] + b01.x, v01 = acc[mt][nt][1] + b01.y;
            float v10 = acc[mt][nt][2] + b01.x, v11 = acc[mt][nt][3] + b01.y;
            if (sizeof(OutT) == 4) {
                float* cp = (float*)Cm;
                *reinterpret_cast<float2*>(cp + (size_t)m * N + n) = make_float2(v00, v01);
                *reinterpret_cast<float2*>(cp + (size_t)(m + 8) * N + n) = make_float2(v10, v11);
            } else {
                __half* cp = (__half*)Cm;
                *reinterpret_cast<__half2*>(cp + (size_t)m * N + n) = __floats2half2_rn(v00, v01);
                *reinterpret_cast<__half2*>(cp + (size_t)(m + 8) * N + n) = __floats2half2_rn(v10, v11);
            }
        }
    }
}

// ---------------- kernel 3: attention (S=4, per-batch block), fp16 qkv in, fp16 split out ----------------
__global__ __launch_bounds__(256)
void attn_kernel() {
    __shared__ float Ks[4][DD];
    __shared__ float Vs[4][DD];
    __shared__ float Sc[HH][4][4];
    int b = blockIdx.x, tid = threadIdx.x;
    const __half* base = g_qkvh + (size_t)b * 4 * 3 * DD;
    for (int t = 0; t < 4; t++) {
        const __half2* k2 = reinterpret_cast<const __half2*>(base + (size_t)t * 3 * DD + DD);
        const __half2* v2 = reinterpret_cast<const __half2*>(base + (size_t)t * 3 * DD + 2 * DD);
        for (int i = tid; i < DD / 2; i += 256) {
            float2 kf = __half22float2(k2[i]);
            float2 vf = __half22float2(v2[i]);
            Ks[t][2 * i] = kf.x; Ks[t][2 * i + 1] = kf.y;
            Vs[t][2 * i] = vf.x; Vs[t][2 * i + 1] = vf.y;
        }
    }
    __syncthreads();
    int warp = tid >> 5, lane = tid & 31;
    #pragma unroll
    for (int d8 = 0; d8 < 8; d8++) {
        int id = warp * 8 + d8;          // 0..63
        int h = id >> 4, tq = (id >> 2) & 3, tk = id & 3;
        const __half2* qrow = reinterpret_cast<const __half2*>(base + (size_t)tq * 3 * DD + h * HD);
        float s = 0.f;
        #pragma unroll
        for (int i = lane; i < HD / 2; i += 32) {
            float2 qf = __half22float2(qrow[i]);
            s += qf.x * Ks[tk][h * HD + 2 * i] + qf.y * Ks[tk][h * HD + 2 * i + 1];
        }
        #pragma unroll
        for (int o = 16; o; o >>= 1) s += __shfl_xor_sync(0xffffffffu, s, o);
        if (lane == 0) Sc[h][tq][tk] = s * (1.0f / 16.0f);
    }
    __syncthreads();
    if (tid < 16) {
        int h = tid >> 2, tq = tid & 3;
        float m = Sc[h][tq][0];
        #pragma unroll
        for (int k = 1; k < 4; k++) m = fmaxf(m, Sc[h][tq][k]);
        float e[4], se = 0.f;
        #pragma unroll
        for (int k = 0; k < 4; k++) { e[k] = expf(Sc[h][tq][k] - m); se += e[k]; }
        #pragma unroll
        for (int k = 0; k < 4; k++) Sc[h][tq][k] = e[k] / se;
    }
    __syncthreads();
    #pragma unroll
    for (int t = 0; t < 4; t++) {
        for (int i = tid; i < DD; i += 256) {
            int h = i >> 8;
            float a = 0.f;
            #pragma unroll
            for (int tk = 0; tk < 4; tk++) a = fmaf(Sc[h][t][tk], Vs[tk][i], a);
            size_t idx = ((size_t)b * 4 + t) * DD + i;
            __half hh = __float2half_rn(a);
            __half hl = __float2half_rn(a - __half2float(hh));
            g_ah[idx] = hh;
            g_al[idx] = hl;
        }
    }
}

// ---------------- kernel 5: residual + LN + split + l_expmap0 ----------------
__global__ void ln_split_kernel(const float* __restrict__ lnw, const float* __restrict__ lnb,
                                float* __restrict__ out) {
    __shared__ float sm[32];
    int row = blockIdx.x;           // b*4 + t
    int b = row >> 2, t = row & 3;
    int tid = threadIdx.x;
    float4 x = reinterpret_cast<const float4*>(g_gf + (size_t)row * DD)[tid];
    float4 a = reinterpret_cast<const float4*>(g_attn2 + (size_t)row * DD)[tid];
    x.x += a.x; x.y += a.y; x.z += a.z; x.w += a.w;
    float s  = x.x + x.y + x.z + x.w;
    float sq = x.x*x.x + x.y*x.y + x.z*x.z + x.w*x.w;
    float sum = blockReduceSum256(s, sm);
    float sumsq = blockReduceSum256(sq, sm);
    float mu = sum * (1.0f / DD);
    float var = sumsq * (1.0f / DD) - mu * mu;
    float rstd = rsqrtf(var + 1e-5f);
    float4 w = reinterpret_cast<const float4*>(lnw)[tid];
    float4 bb = reinterpret_cast<const float4*>(lnb)[tid];
    float4 y;
    y.x = (x.x - mu) * rstd * w.x + bb.x;
    y.y = (x.y - mu) * rstd * w.y + bb.y;
    y.z = (x.z - mu) * rstd * w.z + bb.z;
    y.w = (x.w - mu) * rstd * w.w + bb.w;
    if (t >= 2) {
        float* dst = out + (t == 2 ? OFF_OEU : OFF_FEU) + (size_t)b * DD + (size_t)tid * 4;
        dst[0] = y.x; dst[1] = y.y; dst[2] = y.z; dst[3] = y.w;
    } else {
        float n2 = blockReduceSum256(y.x*y.x + y.y*y.y + y.z*y.z + y.w*y.w, sm);
        float rc = SQC * sqrtf(n2);
        float si = fminf(fmaxf(rc, EPS8), ASINH_MAXF);
        float scl = sinhf(si) / fmaxf(rc, EPS8);
        float* dst = out + (t == 0 ? OFF_OH : OFF_FH) + (size_t)b * DD + (size_t)tid * 4;
        dst[0] = y.x * scl; dst[1] = y.y * scl; dst[2] = y.z * scl; dst[3] = y.w * scl;
        if (tid == 0) {
            float on2 = scl * scl * n2;
            if (t == 0) g_ohn2[b] = on2; else g_fhn2[b] = on2;
        }
    }
}

// ---------------- kernel 7: per-row penalty ----------------
__device__ __forceinline__ float penalty_scalar(float F2, float FY, float yn2) {
    float nF = sqrtf(F2);
    float rc = SQC * nF;
    float si = fminf(fmaxf(rc, EPS8), ASINH_MAXF);
    float s = sinhf(si) / fmaxf(rc, EPS8);
    float x2 = s * s * F2;
    float nx = s * nF;
    float xy = s * FY;
    float xt = sqrtf(1.0f / CURVF + x2);
    float yt = sqrtf(1.0f / CURVF + yn2);
    float cxyl = CURVF * (xy - xt * yt);
    float num = yt + cxyl * xt;
    float den = sqrtf(fmaxf(cxyl * cxyl - 1.0f, EPS8));
    float ai = num / (nx * den + EPS8);
    ai = fminf(fmaxf(ai, -1.f + EPS8), 1.f - EPS8);
    float ang = acosf(ai);
    float asin_in = 0.2f / (nx * SQC + EPS8);
    asin_in = fminf(fmaxf(asin_in, -1.f + EPS8), 1.f - EPS8);
    float ap = asinf(asin_in);
    return fmaxf(ang - ap, 0.f);
}

__global__ void loss_kernel(const int* __restrict__ mask, const float* __restrict__ out) {
    __shared__ float sm[32];
    int b = blockIdx.x, tid = threadIdx.x;
    const float* OF = g_OF + (size_t)b * DD;
    const float* FF = g_FF + (size_t)b * DD;
    const float* fh = out + OFF_FH + (size_t)b * DD;
    const float* oh = out + OFF_OH + (size_t)b * DD;
    float doo = 0.f, doy = 0.f, dff = 0.f, dfy = 0.f;
    for (int i = tid; i < DD; i += 256) {
        float o = OF[i], f = FF[i];
        doo += o * o; doy += o * fh[i];
        dff += f * f; dfy += f * oh[i];
    }
    doo = blockReduceSum256(doo, sm);
    doy = blockReduceSum256(doy, sm);
    dff = blockReduceSum256(dff, sm);
    dfy = blockReduceSum256(dfy, sm);
    if (tid == 0) {
        g_ordpen[b] = penalty_scalar(doo, doy, g_fhn2[b]);
        g_fampen[b] = penalty_scalar(dff, dfy, g_ohn2[b]) * (float)mask[b];
    }
}

// ---------------- kernel 8: deterministic loss reduction ----------------
__global__ void loss_reduce_kernel(const int* __restrict__ mask, float* __restrict__ out) {
    __shared__ float smo[1024];
    __shared__ float smf[1024];
    __shared__ int   smc[1024];
    int tid = threadIdx.x;
    float so = 0.f, sf = 0.f; int c = 0;
    for (int i = tid; i < BB; i += 1024) { so += g_ordpen[i]; sf += g_fampen[i]; c += mask[i]; }
    smo[tid] = so; smf[tid] = sf; smc[tid] = c;
    __syncthreads();
    for (int st = 512; st; st >>= 1) {
        if (tid < st) { smo[tid] += smo[tid + st]; smf[tid] += smf[tid + st]; smc[tid] += smc[tid + st]; }
        __syncthreads();
    }
    if (tid == 0) {
        float ol = smo[0] / (float)BB;
        float cnt = (float)smc[0];
        float fl = (cnt > 0.f) ? smf[0] / fmaxf(cnt, 1.f) : 0.f;
        out[OFF_LOSS] = ol + fl;
    }
}

// ---------------- kernel 9: MLR precompute (per-class scalars) ----------------
__global__ void mlr_prep_kernel(const float* __restrict__ a, const float* __restrict__ p) {
    int warp = threadIdx.x >> 5, lane = threadIdx.x & 31;
    int c = warp; // 16 warps
    const float* pr = p + (size_t)c * DD;
    const float* ar = a + (size_t)c * DD;
    float pn2 = 0.f, pa0 = 0.f, an2 = 0.f;
    for (int i = lane; i < DD; i += 32) {
        float pv = pr[i], av = ar[i];
        pn2 += pv * pv; pa0 += pv * av; an2 += av * av;
    }
    #pragma unroll
    for (int o = 16; o; o >>= 1) {
        pn2 += __shfl_xor_sync(0xffffffffu, pn2, o);
        pa0 += __shfl_xor_sync(0xffffffffu, pa0, o);
        an2 += __shfl_xor_sync(0xffffffffu, an2, o);
    }
    float n = fmaxf(sqrtf(pn2), 1e-15f);
    float t = SQC * n;
    float scl = tanhf(t) / (SQC * n);      // p_expmap0 scale
    float pp2 = scl * scl * pn2;
    float conf = 1.0f - CURVF * pp2;
    for (int i = lane; i < DD; i += 32) {
        g_pp[(size_t)c * DD + i] = pr[i] * scl;
        g_ap[(size_t)c * DD + i] = ar[i] * conf;
    }
    if (lane == 0) {
        float pa = conf * scl * pa0;       // p_p . a_p
        float an = fabsf(conf) * sqrtf(an2);
        float lam = 2.0f / (1.0f - CURVF * pp2);
        g_pp2[c] = pp2; g_pa[c] = pa; g_Bc[c] = conf; g_an[c] = an;
        g_kk[c] = lam * an / SQC;
    }
}

// ---------------- kernel 10: MLR logits (8 batches/block, pp/ap in registers) ----------------
#define MLRB 8
__global__ __launch_bounds__(512)
void mlr_kernel(float* __restrict__ out) {
    __shared__ float xs[MLRB][DD];
    __shared__ float ssg[MLRB];
    __shared__ float sn2[MLRB];
    int b0 = blockIdx.x * MLRB;
    int tid = threadIdx.x;
    #pragma unroll
    for (int t = 0; t < MLRB; t++) {
        const float* oh = out + OFF_OH + (size_t)(b0 + t) * DD;
        for (int i = tid; i < DD; i += 512) xs[t][i] = oh[i];
    }
    if (tid < MLRB) {
        float ohn2 = g_ohn2[b0 + tid];
        float n0 = sqrtf(fmaxf(ohn2, 0.f));
        float rc = SQC * n0;
        float s1 = asinhf(rc) / fmaxf(rc, EPS8);
        float nU = s1 * n0;
        float nUc = fmaxf(nU, 1e-15f);
        float s2 = tanhf(SQC * nUc) / (SQC * nUc);
        float nV = s2 * nU;
        float maxn = 0.996f / SQC;
        float nVc = fmaxf(nV, 1e-15f);
        float s3 = (nVc > maxn) ? (maxn / nVc) : 1.0f;
        ssg[tid] = s1 * s2 * s3;
        sn2[tid] = ohn2;
    }
    __syncthreads();

    int c = tid >> 5, lane = tid & 31;   // 16 warps = 16 classes
    float rpp[32], rap[32];
    #pragma unroll
    for (int j = 0; j < 32; j++) {
        rpp[j] = g_pp[(size_t)c * DD + j * 32 + lane];
        rap[j] = g_ap[(size_t)c * DD + j * 32 + lane];
    }
    float x2 = g_pp2[c], Bc = g_Bc[c], pa = g_pa[c], an = g_an[c], kk = g_kk[c];

    #pragma unroll
    for (int t = 0; t < MLRB; t++) {
        float dp = 0.f, da = 0.f;
        #pragma unroll
        for (int j = 0; j < 32; j++) {
            float xv = xs[t][j * 32 + lane];
            dp += xv * rpp[j];
            da += xv * rap[j];
        }
        #pragma unroll
        for (int o = 16; o; o >>= 1) {
            dp += __shfl_xor_sync(0xffffffffu, dp, o);
            da += __shfl_xor_sync(0xffffffffu, da, o);
        }
        if (lane == 0) {
            float sG = ssg[t];
            float xy = -sG * dp;
            float xa =  sG * da;
            float y2 = sG * sG * sn2[t];
            float A = 1.0f + 2.0f * CURVF * xy + CURVF * y2;
            float den = 1.0f + 2.0f * CURVF * xy + CURVF * CURVF * x2 * y2;
            float denp = den + 1e-5f;
            float mdot = (-A * pa + Bc * xa) / denp;
            float num = 2.0f * SQC * mdot;
            float mob2 = (A * A * x2 + 2.0f * A * Bc * xy + Bc * Bc * y2) / (denp * denp);
            float dml = an * (1.0f - CURVF * mob2);
            out[(size_t)(b0 + t) * CC + c] = kk * asinhf(num / dml);
        }
    }
}

// ---------------- host ----------------
extern "C" void kernel_launch(void* const* d_in, const int* in_sizes, int n_in,
                              void* d_out, int out_size) {
    const float* order_hyp  = (const float*)d_in[0];
    const float* family_hyp = (const float*)d_in[1];
    const float* order_euc  = (const float*)d_in[2];
    const float* family_euc = (const float*)d_in[3];
    const float* order_in   = (const float*)d_in[4];
    const float* family_in  = (const float*)d_in[5];
    const int*   mask       = (const int*)d_in[6];
    const float* in_proj_w  = (const float*)d_in[7];
    const float* in_proj_b  = (const float*)d_in[8];
    const float* out_proj_w = (const float*)d_in[9];
    const float* out_proj_b = (const float*)d_in[10];
    const float* ln_w       = (const float*)d_in[11];
    const float* ln_b       = (const float*)d_in[12];
    const float* to_w       = (const float*)d_in[13];
    const float* to_b       = (const float*)d_in[14];
    const float* tf_w       = (const float*)d_in[15];
    const float* tf_b       = (const float*)d_in[16];
    const float* mlr_a      = (const float*)d_in[17];
    const float* mlr_p      = (const float*)d_in[18];
    float* out = (float*)d_out;

    float *attn2, *OFp, *FFp;
    __half *qkvh, *ah, *al, *wh;
    cudaGetSymbolAddress((void**)&qkvh,  g_qkvh);
    cudaGetSymbolAddress((void**)&attn2, g_attn2);
    cudaGetSymbolAddress((void**)&OFp,   g_OF);
    cudaGetSymbolAddress((void**)&FFp,   g_FF);
    cudaGetSymbolAddress((void**)&ah,    g_ah);
    cudaGetSymbolAddress((void**)&al,    g_al);
    cudaGetSymbolAddress((void**)&wh,    g_wh);

    cudaFuncSetAttribute(gemm_mma<float>, cudaFuncAttributeMaxDynamicSharedMemorySize, GEMM_DYN_SMEM);
    cudaFuncSetAttribute(gemm_mma<__half>, cudaFuncAttributeMaxDynamicSharedMemorySize, GEMM_DYN_SMEM);

    auto splitA = [&](const float* src, size_t n) {
        int n4 = (int)(n / 4);
        split_f16<<<(n4 + 255) / 256, 256>>>((const float4*)src, (uint2*)ah, (uint2*)al, n4);
    };
    auto convW = [&](const float* src, size_t n) {
        int n4 = (int)(n / 4);
        conv_f16<<<(n4 + 255) / 256, 256>>>((const float4*)src, (uint2*)wh, n4);
    };

    // 1. hyperbolic logmap + stack -> gf (+ fused fp16 hi/lo split of A)
    build_gf_kernel<<<BB, 256>>>(order_hyp, family_hyp, order_euc, family_euc);

    // 2. QKV GEMM: (16384,1024) x (3072,1024)^T -> fp16 qkv
    convW(in_proj_w, (size_t)3 * DD * DD);
    gemm_mma<__half><<<dim3((3 * DD) / TCBN, (BB * 4) / TCBM), 512, GEMM_DYN_SMEM>>>(
        ah, al, wh, in_proj_b, qkvh, BB * 4, 3 * DD, DD);

    // 3. attention (reads fp16 qkv, writes fp16 hi/lo A directly)
    attn_kernel<<<BB, 256>>>();

    // 4. out-proj GEMM (fp32 out)
    convW(out_proj_w, (size_t)DD * DD);
    gemm_mma<float><<<dim3(DD / TCBN, (BB * 4) / TCBM), 512, GEMM_DYN_SMEM>>>(
        ah, al, wh, out_proj_b, attn2, BB * 4, DD, DD);

    // 5. residual + LN + split + l_expmap0
    ln_split_kernel<<<BB * 4, 256>>>(ln_w, ln_b, out);

    // 6. feature GEMMs: (4096,768) x (1024,768)^T
    splitA(order_in, (size_t)BB * TT);
    convW(to_w, (size_t)DD * TT);
    gemm_mma<float><<<dim3(DD / TCBN, BB / TCBM), 512, GEMM_DYN_SMEM>>>(
        ah, al, wh, to_b, OFp, BB, DD, TT);
    splitA(family_in, (size_t)BB * TT);
    convW(tf_w, (size_t)DD * TT);
    gemm_mma<float><<<dim3(DD / TCBN, BB / TCBM), 512, GEMM_DYN_SMEM>>>(
        ah, al, wh, tf_b, FFp, BB, DD, TT);

    // 7-8. loss
    loss_kernel<<<BB, 256>>>(mask, out);
    loss_reduce_kernel<<<1, 1024>>>(mask, out);

    // 9-10. MLR logits
    mlr_prep_kernel<<<1, 512>>>(mlr_a, mlr_p);
    mlr_kernel<<<BB / MLRB, 512>>>(out);

    (void)in_sizes; (void)n_in; (void)out_size;
}

// round 13
// speedup vs baseline: 3.6308x; 1.1031x over previous
#include <cuda_runtime.h>
#include <cuda_fp16.h>
#include <math.h>
#include <stdint.h>
#include <stddef.h>

// ---------------- problem constants ----------------
#define BB 4096
#define DD 1024
#define TT 768
#define CC 16
#define HH 4
#define HD 256
#define CURVF 0.05f
#define SQC 0.22360679774997896f   /* sqrt(0.05) */
#define EPS8 1e-8f
#define ASINH_MAXF 11.090354888959125f /* asinh(2^15) */

// output layout (flat float32, tuple order):
// logits (B*C) | hyp_loss (1) | oh (B*D) | fh (B*D) | oeu (B*D) | feu (B*D)
#define OFF_LOGITS 0
#define OFF_LOSS   ((size_t)BB*CC)
#define OFF_OH     (OFF_LOSS + 1)
#define OFF_FH     (OFF_OH + (size_t)BB*DD)
#define OFF_OEU    (OFF_FH + (size_t)BB*DD)
#define OFF_FEU    (OFF_OEU + (size_t)BB*DD)

// ---------------- device scratch (static, allocation-free) ----------------
__device__ float g_gf[(size_t)BB*4*DD];          // (B,4,D)
__device__ __half g_qkvh[(size_t)BB*4*3*DD];     // QKV in fp16
__device__ float g_attn2[(size_t)BB*4*DD];       // out-proj output
__device__ float g_OF[(size_t)BB*DD];
__device__ float g_FF[(size_t)BB*DD];
__device__ float g_ohn2[BB];
__device__ float g_fhn2[BB];
__device__ float g_ordpen[BB];
__device__ float g_fampen[BB];
__device__ float g_pp[CC*DD];
__device__ float g_ap[CC*DD];
__device__ float g_pp2[CC];
__device__ float g_pa[CC];
__device__ float g_Bc[CC];
__device__ float g_an[CC];
__device__ float g_kk[CC];
// fp16 GEMM operand scratch: A hi/lo (up to 16384x1024), W hi (up to 3072x1024)
__device__ __half g_ah[(size_t)BB*4*DD];
__device__ __half g_al[(size_t)BB*4*DD];
__device__ __half g_wh[(size_t)3*DD*DD];

// ---------------- PTX helpers (baseline sm_103 ISA: mma.sync/ldmatrix/cp.async) ----------------
__device__ __forceinline__ uint32_t smem_u32(const void* p) {
    uint32_t a;
    asm("{ .reg .u64 t; cvta.to.shared.u64 t, %1; cvt.u32.u64 %0, t; }" : "=r"(a) : "l"(p));
    return a;
}
#define SWZ(o) ((uint32_t)(o) ^ ((((uint32_t)(o)) >> 3) & 0x70u))
#define CP_ASYNC16(dst, src) \
    asm volatile("cp.async.cg.shared.global [%0], [%1], 16;" :: "r"(dst), "l"(src))
#define CP_COMMIT() asm volatile("cp.async.commit_group;" ::: "memory")
#define CP_WAIT2()  asm volatile("cp.async.wait_group 2;" ::: "memory")
#define CP_WAIT1()  asm volatile("cp.async.wait_group 1;" ::: "memory")
#define CP_WAIT0()  asm volatile("cp.async.wait_group 0;" ::: "memory")
#define LDMX4(r0, r1, r2, r3, a) \
    asm volatile("ldmatrix.sync.aligned.m8n8.x4.shared.b16 {%0,%1,%2,%3}, [%4];" \
                 : "=r"(r0), "=r"(r1), "=r"(r2), "=r"(r3) : "r"(a))
#define LDMX2(r0, r1, a) \
    asm volatile("ldmatrix.sync.aligned.m8n8.x2.shared.b16 {%0,%1}, [%2];" \
                 : "=r"(r0), "=r"(r1) : "r"(a))
#define MMAF16(d, a0, a1, a2, a3, b0, b1) \
    asm volatile("mma.sync.aligned.m16n8k16.row.col.f32.f16.f16.f32 " \
                 "{%0,%1,%2,%3}, {%4,%5,%6,%7}, {%8,%9}, {%0,%1,%2,%3};" \
                 : "+f"((d)[0]), "+f"((d)[1]), "+f"((d)[2]), "+f"((d)[3]) \
                 : "r"(a0), "r"(a1), "r"(a2), "r"(a3), "r"(b0), "r"(b1))

// ---------------- helpers ----------------
__device__ __forceinline__ float blockReduceSum256(float v, float* sm32) {
    int tid = threadIdx.x;
    #pragma unroll
    for (int o = 16; o; o >>= 1) v += __shfl_xor_sync(0xffffffffu, v, o);
    if ((tid & 31) == 0) sm32[tid >> 5] = v;
    __syncthreads();
    float r = 0.f;
    if (tid < 8) r = sm32[tid];
    if (tid < 32) {
        #pragma unroll
        for (int o = 4; o; o >>= 1) r += __shfl_xor_sync(0xffffffffu, r, o);
    }
    if (tid == 0) sm32[0] = r;
    __syncthreads();
    r = sm32[0];
    __syncthreads();
    return r;
}

__device__ __forceinline__ void split4h(float4 v, uint2& H, uint2& L) {
    __half h0 = __float2half_rn(v.x), h1 = __float2half_rn(v.y),
           h2 = __float2half_rn(v.z), h3 = __float2half_rn(v.w);
    __half l0 = __float2half_rn(v.x - __half2float(h0));
    __half l1 = __float2half_rn(v.y - __half2float(h1));
    __half l2 = __float2half_rn(v.z - __half2float(h2));
    __half l3 = __float2half_rn(v.w - __half2float(h3));
    H.x = ((uint32_t)__half_as_ushort(h1) << 16) | __half_as_ushort(h0);
    H.y = ((uint32_t)__half_as_ushort(h3) << 16) | __half_as_ushort(h2);
    L.x = ((uint32_t)__half_as_ushort(l1) << 16) | __half_as_ushort(l0);
    L.y = ((uint32_t)__half_as_ushort(l3) << 16) | __half_as_ushort(l2);
}

// ---------------- fp32 -> fp16 hi/lo split (A operands) ----------------
__global__ void split_f16(const float4* __restrict__ x, uint2* __restrict__ hi,
                          uint2* __restrict__ lo, int n4) {
    int i = blockIdx.x * 256 + threadIdx.x;
    if (i >= n4) return;
    uint2 H, L;
    split4h(x[i], H, L);
    hi[i] = H;
    lo[i] = L;
}

// ---------------- fp32 -> fp16 convert (W operands, hi only) ----------------
__global__ void conv_f16(const float4* __restrict__ x, uint2* __restrict__ h, int n4) {
    int i = blockIdx.x * 256 + threadIdx.x;
    if (i >= n4) return;
    float4 v = x[i];
    __half h0 = __float2half_rn(v.x), h1 = __float2half_rn(v.y),
           h2 = __float2half_rn(v.z), h3 = __float2half_rn(v.w);
    uint2 H;
    H.x = ((uint32_t)__half_as_ushort(h1) << 16) | __half_as_ushort(h0);
    H.y = ((uint32_t)__half_as_ushort(h3) << 16) | __half_as_ushort(h2);
    h[i] = H;
}

// ---------------- kernel 1: p_logmap0 rows -> gf (B,4,D) + fused fp16 split ----------------
__global__ void build_gf_kernel(const float* __restrict__ ohp, const float* __restrict__ fhp,
                                const float* __restrict__ oeu, const float* __restrict__ feu) {
    __shared__ float sm[32];
    int b = blockIdx.x, tid = threadIdx.x;
    #pragma unroll
    for (int r = 0; r < 2; r++) {
        const float* src = (r == 0 ? ohp : fhp) + (size_t)b * DD;
        float4 v = reinterpret_cast<const float4*>(src)[tid];
        float s2 = v.x*v.x + v.y*v.y + v.z*v.z + v.w*v.w;
        float n2 = blockReduceSum256(s2, sm);
        float n = fmaxf(sqrtf(n2), 1e-15f);
        float t = SQC * n;
        float tc = fminf(fmaxf(t, -1.f + 1e-5f), 1.f - 1e-5f);
        float art = 0.5f * (log1pf(tc) - log1pf(-tc));
        float scl = art / (n * SQC);
        float4 o = make_float4(v.x*scl, v.y*scl, v.z*scl, v.w*scl);
        size_t row = (size_t)b * 4 + r;
        reinterpret_cast<float4*>(g_gf + row * DD)[tid] = o;
        uint2 H, L;
        split4h(o, H, L);
        reinterpret_cast<uint2*>(g_ah + row * DD)[tid] = H;
        reinterpret_cast<uint2*>(g_al + row * DD)[tid] = L;
    }
    #pragma unroll
    for (int r = 2; r < 4; r++) {
        const float* src = (r == 2 ? oeu : feu) + (size_t)b * DD;
        float4 v = reinterpret_cast<const float4*>(src)[tid];
        size_t row = (size_t)b * 4 + r;
        reinterpret_cast<float4*>(g_gf + row * DD)[tid] = v;
        uint2 H, L;
        split4h(v, H, L);
        reinterpret_cast<uint2*>(g_ah + row * DD)[tid] = H;
        reinterpret_cast<uint2*>(g_al + row * DD)[tid] = L;
    }
}

// ---------------- kernel 2: mma.sync 2-pass fp16 NT GEMM ----------------
// CTA tile 128x256, warp tile 64x64 (2x4 warps, 256 threads), 3-stage cp.async.
// C(M,N) = A(M,K)*W(N,K)^T + bias;  A as fp16 hi/lo split, W as single fp16.
// M%128==0, N%256==0, K%64==0.  OutT = float or __half.
#define TCBM 128
#define TCBN 256
#define TCBK 64
#define AT_B 16384                    /* A tile: 128 rows x 128B */
#define WT_B 32768                    /* W tile: 256 rows x 128B */
#define STAGE_B (2*AT_B + WT_B)       /* Ah, Al, Wh = 65536 */
#define OFF_AL AT_B
#define OFF_W  (2*AT_B)
#define GEMM_DYN_SMEM (3*STAGE_B)     /* 196608 */

template <typename OutT>
__global__ __launch_bounds__(256, 1)
void gemm_mma(const __half* __restrict__ Ahi, const __half* __restrict__ Alo,
              const __half* __restrict__ Wh,
              const float* __restrict__ bias, OutT* __restrict__ Cm,
              int M, int N, int K) {
    extern __shared__ char smem[];
    uint32_t sb = smem_u32(smem);
    int tid = threadIdx.x, wid = tid >> 5, lane = tid & 31;
    int warp_m = wid >> 2, warp_n = wid & 3;   // 2x4 warps, warp tile 64x64
    int bm = blockIdx.y * TCBM, bn = blockIdx.x * TCBN;

    float acc[4][8][4];
    #pragma unroll
    for (int i = 0; i < 4; i++)
        #pragma unroll
        for (int j = 0; j < 8; j++)
            #pragma unroll
            for (int r = 0; r < 4; r++) acc[i][j][r] = 0.f;

    const int NC = K / TCBK;
    // load maps: A tiles have 1024 16B-segs (4 slots/thread), W tile 2048 (8 slots/thread)
    const ptrdiff_t dAL = Alo - Ahi;
    const __half* pA[4];
    uint32_t swA[4];
    #pragma unroll
    for (int it = 0; it < 4; it++) {
        int slot = tid + it * 256;
        int row = slot >> 3, seg = slot & 7;
        swA[it] = SWZ(row * 128 + seg * 16);
        pA[it] = Ahi + (size_t)(bm + row) * K + seg * 8;
    }
    const __half* pW[8];
    uint32_t swW[8];
    #pragma unroll
    for (int it = 0; it < 8; it++) {
        int slot = tid + it * 256;
        int row = slot >> 3, seg = slot & 7;
        swW[it] = SWZ(row * 128 + seg * 16);
        pW[it] = Wh + (size_t)(bn + row) * K + seg * 8;
    }

    auto prefetch = [&](uint32_t st, int k0) {
        #pragma unroll
        for (int it = 0; it < 4; it++) {
            CP_ASYNC16(st + swA[it], pA[it] + k0);
            CP_ASYNC16(st + OFF_AL + swA[it], pA[it] + dAL + k0);
        }
        #pragma unroll
        for (int it = 0; it < 8; it++)
            CP_ASYNC16(st + OFF_W + swW[it], pW[it] + k0);
    };

    prefetch(sb, 0);
    CP_COMMIT();
    prefetch(sb + STAGE_B, TCBK);
    CP_COMMIT();

    for (int i = 0; i < NC; i++) {
        int rem = NC - 1 - i;
        if (rem >= 2) {
            prefetch(sb + (uint32_t)((i + 2) % 3) * STAGE_B, (i + 2) * TCBK);
            CP_COMMIT();
            CP_WAIT2();
        } else if (rem == 1) {
            CP_WAIT1();
        } else {
            CP_WAIT0();
        }
        __syncthreads();

        uint32_t st = sb + (uint32_t)(i % 3) * STAGE_B;
        #pragma unroll
        for (int ks = 0; ks < 4; ks++) {
            uint32_t ah[4][4], al[4][4], bh[8][2];
            int arow = warp_m * 64 + (lane & 15);
            int ak = (ks * 16 + ((lane >> 4) << 3)) * 2;
            #pragma unroll
            for (int mt = 0; mt < 4; mt++) {
                uint32_t off = SWZ((arow + mt * 16) * 128 + ak);
                LDMX4(ah[mt][0], ah[mt][1], ah[mt][2], ah[mt][3], st + off);
                LDMX4(al[mt][0], al[mt][1], al[mt][2], al[mt][3], st + OFF_AL + off);
            }
            int brow = warp_n * 64 + (lane & 7);
            int bk = (ks * 16 + (((lane >> 3) & 1) << 3)) * 2;
            #pragma unroll
            for (int nt = 0; nt < 8; nt++) {
                uint32_t off = SWZ((brow + nt * 8) * 128 + bk);
                LDMX2(bh[nt][0], bh[nt][1], st + OFF_W + off);
            }
            #pragma unroll
            for (int mt = 0; mt < 4; mt++)
                #pragma unroll
                for (int nt = 0; nt < 8; nt++)
                    MMAF16(acc[mt][nt], ah[mt][0], ah[mt][1], ah[mt][2], ah[mt][3],
                           bh[nt][0], bh[nt][1]);
            #pragma unroll
            for (int mt = 0; mt < 4; mt++)
                #pragma unroll
                for (int nt = 0; nt < 8; nt++)
                    MMAF16(acc[mt][nt], al[mt][0], al[mt][1], al[mt][2], al[mt][3],
                           bh[nt][0], bh[nt][1]);
        }
        __syncthreads();
    }

    // epilogue: bias + store
    #pragma unroll
    for (int mt = 0; mt < 4; mt++) {
        int m = bm + warp_m * 64 + mt * 16 + (lane >> 2);
        #pragma unroll
        for (int nt = 0; nt < 8; nt++) {
            int n = bn + warp_n * 64 + nt * 8 + (lane & 3) * 2;
            float2 b01 = *reinterpret_cast<const float2*>(bias + n);
            float v00 = acc[mt][nt][0] + b01.x, v01 = acc[mt][nt][1] + b01.y;
            float v10 = acc[mt][nt][2] + b01.x, v11 = acc[mt][nt][3] + b01.y;
            if (sizeof(OutT) == 4) {
                float* cp = (float*)Cm;
                *reinterpret_cast<float2*>(cp + (size_t)m * N + n) = make_float2(v00, v01);
                *reinterpret_cast<float2*>(cp + (size_t)(m + 8) * N + n) = make_float2(v10, v11);
            } else {
                __half* cp = (__half*)Cm;
                *reinterpret_cast<__half2*>(cp + (size_t)m * N + n) = __floats2half2_rn(v00, v01);
                *reinterpret_cast<__half2*>(cp + (size_t)(m + 8) * N + n) = __floats2half2_rn(v10, v11);
            }
        }
    }
}

// ---------------- kernel 3: attention (S=4, per-batch block), fp16 qkv in, fp16 split out ----------------
__global__ __launch_bounds__(256)
void attn_kernel() {
    __shared__ float Ks[4][DD];
    __shared__ float Vs[4][DD];
    __shared__ float Sc[HH][4][4];
    int b = blockIdx.x, tid = threadIdx.x;
    const __half* base = g_qkvh + (size_t)b * 4 * 3 * DD;
    for (int t = 0; t < 4; t++) {
        const __half2* k2 = reinterpret_cast<const __half2*>(base + (size_t)t * 3 * DD + DD);
        const __half2* v2 = reinterpret_cast<const __half2*>(base + (size_t)t * 3 * DD + 2 * DD);
        for (int i = tid; i < DD / 2; i += 256) {
            float2 kf = __half22float2(k2[i]);
            float2 vf = __half22float2(v2[i]);
            Ks[t][2 * i] = kf.x; Ks[t][2 * i + 1] = kf.y;
            Vs[t][2 * i] = vf.x; Vs[t][2 * i + 1] = vf.y;
        }
    }
    __syncthreads();
    int warp = tid >> 5, lane = tid & 31;
    #pragma unroll
    for (int d8 = 0; d8 < 8; d8++) {
        int id = warp * 8 + d8;          // 0..63
        int h = id >> 4, tq = (id >> 2) & 3, tk = id & 3;
        const __half2* qrow = reinterpret_cast<const __half2*>(base + (size_t)tq * 3 * DD + h * HD);
        float s = 0.f;
        #pragma unroll
        for (int i = lane; i < HD / 2; i += 32) {
            float2 qf = __half22float2(qrow[i]);
            s += qf.x * Ks[tk][h * HD + 2 * i] + qf.y * Ks[tk][h * HD + 2 * i + 1];
        }
        #pragma unroll
        for (int o = 16; o; o >>= 1) s += __shfl_xor_sync(0xffffffffu, s, o);
        if (lane == 0) Sc[h][tq][tk] = s * (1.0f / 16.0f);
    }
    __syncthreads();
    if (tid < 16) {
        int h = tid >> 2, tq = tid & 3;
        float m = Sc[h][tq][0];
        #pragma unroll
        for (int k = 1; k < 4; k++) m = fmaxf(m, Sc[h][tq][k]);
        float e[4], se = 0.f;
        #pragma unroll
        for (int k = 0; k < 4; k++) { e[k] = expf(Sc[h][tq][k] - m); se += e[k]; }
        #pragma unroll
        for (int k = 0; k < 4; k++) Sc[h][tq][k] = e[k] / se;
    }
    __syncthreads();
    #pragma unroll
    for (int t = 0; t < 4; t++) {
        for (int i2 = tid; i2 < DD / 2; i2 += 256) {
            int i = 2 * i2;
            int h = i >> 8;
            float a0 = 0.f, a1 = 0.f;
            #pragma unroll
            for (int tk = 0; tk < 4; tk++) {
                float w = Sc[h][t][tk];
                a0 = fmaf(w, Vs[tk][i], a0);
                a1 = fmaf(w, Vs[tk][i + 1], a1);
            }
            size_t idx = ((size_t)b * 4 + t) * DD + i;
            __half h0 = __float2half_rn(a0);
            __half h1 = __float2half_rn(a1);
            __half l0 = __float2half_rn(a0 - __half2float(h0));
            __half l1 = __float2half_rn(a1 - __half2float(h1));
            *reinterpret_cast<__half2*>(g_ah + idx) = __halves2half2(h0, h1);
            *reinterpret_cast<__half2*>(g_al + idx) = __halves2half2(l0, l1);
        }
    }
}

// ---------------- kernel 5: residual + LN + split + l_expmap0 ----------------
__global__ void ln_split_kernel(const float* __restrict__ lnw, const float* __restrict__ lnb,
                                float* __restrict__ out) {
    __shared__ float sm[32];
    int row = blockIdx.x;           // b*4 + t
    int b = row >> 2, t = row & 3;
    int tid = threadIdx.x;
    float4 x = reinterpret_cast<const float4*>(g_gf + (size_t)row * DD)[tid];
    float4 a = reinterpret_cast<const float4*>(g_attn2 + (size_t)row * DD)[tid];
    x.x += a.x; x.y += a.y; x.z += a.z; x.w += a.w;
    float s  = x.x + x.y + x.z + x.w;
    float sq = x.x*x.x + x.y*x.y + x.z*x.z + x.w*x.w;
    float sum = blockReduceSum256(s, sm);
    float sumsq = blockReduceSum256(sq, sm);
    float mu = sum * (1.0f / DD);
    float var = sumsq * (1.0f / DD) - mu * mu;
    float rstd = rsqrtf(var + 1e-5f);
    float4 w = reinterpret_cast<const float4*>(lnw)[tid];
    float4 bb = reinterpret_cast<const float4*>(lnb)[tid];
    float4 y;
    y.x = (x.x - mu) * rstd * w.x + bb.x;
    y.y = (x.y - mu) * rstd * w.y + bb.y;
    y.z = (x.z - mu) * rstd * w.z + bb.z;
    y.w = (x.w - mu) * rstd * w.w + bb.w;
    if (t >= 2) {
        float* dst = out + (t == 2 ? OFF_OEU : OFF_FEU) + (size_t)b * DD + (size_t)tid * 4;
        dst[0] = y.x; dst[1] = y.y; dst[2] = y.z; dst[3] = y.w;
    } else {
        float n2 = blockReduceSum256(y.x*y.x + y.y*y.y + y.z*y.z + y.w*y.w, sm);
        float rc = SQC * sqrtf(n2);
        float si = fminf(fmaxf(rc, EPS8), ASINH_MAXF);
        float scl = sinhf(si) / fmaxf(rc, EPS8);
        float* dst = out + (t == 0 ? OFF_OH : OFF_FH) + (size_t)b * DD + (size_t)tid * 4;
        dst[0] = y.x * scl; dst[1] = y.y * scl; dst[2] = y.z * scl; dst[3] = y.w * scl;
        if (tid == 0) {
            float on2 = scl * scl * n2;
            if (t == 0) g_ohn2[b] = on2; else g_fhn2[b] = on2;
        }
    }
}

// ---------------- kernel 7: per-row penalty ----------------
__device__ __forceinline__ float penalty_scalar(float F2, float FY, float yn2) {
    float nF = sqrtf(F2);
    float rc = SQC * nF;
    float si = fminf(fmaxf(rc, EPS8), ASINH_MAXF);
    float s = sinhf(si) / fmaxf(rc, EPS8);
    float x2 = s * s * F2;
    float nx = s * nF;
    float xy = s * FY;
    float xt = sqrtf(1.0f / CURVF + x2);
    float yt = sqrtf(1.0f / CURVF + yn2);
    float cxyl = CURVF * (xy - xt * yt);
    float num = yt + cxyl * xt;
    float den = sqrtf(fmaxf(cxyl * cxyl - 1.0f, EPS8));
    float ai = num / (nx * den + EPS8);
    ai = fminf(fmaxf(ai, -1.f + EPS8), 1.f - EPS8);
    float ang = acosf(ai);
    float asin_in = 0.2f / (nx * SQC + EPS8);
    asin_in = fminf(fmaxf(asin_in, -1.f + EPS8), 1.f - EPS8);
    float ap = asinf(asin_in);
    return fmaxf(ang - ap, 0.f);
}

__global__ void loss_kernel(const int* __restrict__ mask, const float* __restrict__ out) {
    __shared__ float sm[32];
    int b = blockIdx.x, tid = threadIdx.x;
    const float* OF = g_OF + (size_t)b * DD;
    const float* FF = g_FF + (size_t)b * DD;
    const float* fh = out + OFF_FH + (size_t)b * DD;
    const float* oh = out + OFF_OH + (size_t)b * DD;
    float doo = 0.f, doy = 0.f, dff = 0.f, dfy = 0.f;
    for (int i = tid; i < DD; i += 256) {
        float o = OF[i], f = FF[i];
        doo += o * o; doy += o * fh[i];
        dff += f * f; dfy += f * oh[i];
    }
    doo = blockReduceSum256(doo, sm);
    doy = blockReduceSum256(doy, sm);
    dff = blockReduceSum256(dff, sm);
    dfy = blockReduceSum256(dfy, sm);
    if (tid == 0) {
        g_ordpen[b] = penalty_scalar(doo, doy, g_fhn2[b]);
        g_fampen[b] = penalty_scalar(dff, dfy, g_ohn2[b]) * (float)mask[b];
    }
}

// ---------------- kernel 8: deterministic loss reduction ----------------
__global__ void loss_reduce_kernel(const int* __restrict__ mask, float* __restrict__ out) {
    __shared__ float smo[1024];
    __shared__ float smf[1024];
    __shared__ int   smc[1024];
    int tid = threadIdx.x;
    float so = 0.f, sf = 0.f; int c = 0;
    for (int i = tid; i < BB; i += 1024) { so += g_ordpen[i]; sf += g_fampen[i]; c += mask[i]; }
    smo[tid] = so; smf[tid] = sf; smc[tid] = c;
    __syncthreads();
    for (int st = 512; st; st >>= 1) {
        if (tid < st) { smo[tid] += smo[tid + st]; smf[tid] += smf[tid + st]; smc[tid] += smc[tid + st]; }
        __syncthreads();
    }
    if (tid == 0) {
        float ol = smo[0] / (float)BB;
        float cnt = (float)smc[0];
        float fl = (cnt > 0.f) ? smf[0] / fmaxf(cnt, 1.f) : 0.f;
        out[OFF_LOSS] = ol + fl;
    }
}

// ---------------- kernel 9: MLR precompute (per-class scalars) ----------------
__global__ void mlr_prep_kernel(const float* __restrict__ a, const float* __restrict__ p) {
    int warp = threadIdx.x >> 5, lane = threadIdx.x & 31;
    int c = warp; // 16 warps
    const float* pr = p + (size_t)c * DD;
    const float* ar = a + (size_t)c * DD;
    float pn2 = 0.f, pa0 = 0.f, an2 = 0.f;
    for (int i = lane; i < DD; i += 32) {
        float pv = pr[i], av = ar[i];
        pn2 += pv * pv; pa0 += pv * av; an2 += av * av;
    }
    #pragma unroll
    for (int o = 16; o; o >>= 1) {
        pn2 += __shfl_xor_sync(0xffffffffu, pn2, o);
        pa0 += __shfl_xor_sync(0xffffffffu, pa0, o);
        an2 += __shfl_xor_sync(0xffffffffu, an2, o);
    }
    float n = fmaxf(sqrtf(pn2), 1e-15f);
    float t = SQC * n;
    float scl = tanhf(t) / (SQC * n);      // p_expmap0 scale
    float pp2 = scl * scl * pn2;
    float conf = 1.0f - CURVF * pp2;
    for (int i = lane; i < DD; i += 32) {
        g_pp[(size_t)c * DD + i] = pr[i] * scl;
        g_ap[(size_t)c * DD + i] = ar[i] * conf;
    }
    if (lane == 0) {
        float pa = conf * scl * pa0;       // p_p . a_p
        float an = fabsf(conf) * sqrtf(an2);
        float lam = 2.0f / (1.0f - CURVF * pp2);
        g_pp2[c] = pp2; g_pa[c] = pa; g_Bc[c] = conf; g_an[c] = an;
        g_kk[c] = lam * an / SQC;
    }
}

// ---------------- kernel 10: MLR logits (8 batches/block, pp/ap in registers) ----------------
#define MLRB 8
__global__ __launch_bounds__(512)
void mlr_kernel(float* __restrict__ out) {
    __shared__ float xs[MLRB][DD];
    __shared__ float ssg[MLRB];
    __shared__ float sn2[MLRB];
    int b0 = blockIdx.x * MLRB;
    int tid = threadIdx.x;
    #pragma unroll
    for (int t = 0; t < MLRB; t++) {
        const float* oh = out + OFF_OH + (size_t)(b0 + t) * DD;
        for (int i = tid; i < DD; i += 512) xs[t][i] = oh[i];
    }
    if (tid < MLRB) {
        float ohn2 = g_ohn2[b0 + tid];
        float n0 = sqrtf(fmaxf(ohn2, 0.f));
        float rc = SQC * n0;
        float s1 = asinhf(rc) / fmaxf(rc, EPS8);
        float nU = s1 * n0;
        float nUc = fmaxf(nU, 1e-15f);
        float s2 = tanhf(SQC * nUc) / (SQC * nUc);
        float nV = s2 * nU;
        float maxn = 0.996f / SQC;
        float nVc = fmaxf(nV, 1e-15f);
        float s3 = (nVc > maxn) ? (maxn / nVc) : 1.0f;
        ssg[tid] = s1 * s2 * s3;
        sn2[tid] = ohn2;
    }
    __syncthreads();

    int c = tid >> 5, lane = tid & 31;   // 16 warps = 16 classes
    float rpp[32], rap[32];
    #pragma unroll
    for (int j = 0; j < 32; j++) {
        rpp[j] = g_pp[(size_t)c * DD + j * 32 + lane];
        rap[j] = g_ap[(size_t)c * DD + j * 32 + lane];
    }
    float x2 = g_pp2[c], Bc = g_Bc[c], pa = g_pa[c], an = g_an[c], kk = g_kk[c];

    #pragma unroll
    for (int t = 0; t < MLRB; t++) {
        float dp = 0.f, da = 0.f;
        #pragma unroll
        for (int j = 0; j < 32; j++) {
            float xv = xs[t][j * 32 + lane];
            dp += xv * rpp[j];
            da += xv * rap[j];
        }
        #pragma unroll
        for (int o = 16; o; o >>= 1) {
            dp += __shfl_xor_sync(0xffffffffu, dp, o);
            da += __shfl_xor_sync(0xffffffffu, da, o);
        }
        if (lane == 0) {
            float sG = ssg[t];
            float xy = -sG * dp;
            float xa =  sG * da;
            float y2 = sG * sG * sn2[t];
            float A = 1.0f + 2.0f * CURVF * xy + CURVF * y2;
            float den = 1.0f + 2.0f * CURVF * xy + CURVF * CURVF * x2 * y2;
            float denp = den + 1e-5f;
            float mdot = (-A * pa + Bc * xa) / denp;
            float num = 2.0f * SQC * mdot;
            float mob2 = (A * A * x2 + 2.0f * A * Bc * xy + Bc * Bc * y2) / (denp * denp);
            float dml = an * (1.0f - CURVF * mob2);
            out[(size_t)(b0 + t) * CC + c] = kk * asinhf(num / dml);
        }
    }
}

// ---------------- host ----------------
extern "C" void kernel_launch(void* const* d_in, const int* in_sizes, int n_in,
                              void* d_out, int out_size) {
    const float* order_hyp  = (const float*)d_in[0];
    const float* family_hyp = (const float*)d_in[1];
    const float* order_euc  = (const float*)d_in[2];
    const float* family_euc = (const float*)d_in[3];
    const float* order_in   = (const float*)d_in[4];
    const float* family_in  = (const float*)d_in[5];
    const int*   mask       = (const int*)d_in[6];
    const float* in_proj_w  = (const float*)d_in[7];
    const float* in_proj_b  = (const float*)d_in[8];
    const float* out_proj_w = (const float*)d_in[9];
    const float* out_proj_b = (const float*)d_in[10];
    const float* ln_w       = (const float*)d_in[11];
    const float* ln_b       = (const float*)d_in[12];
    const float* to_w       = (const float*)d_in[13];
    const float* to_b       = (const float*)d_in[14];
    const float* tf_w       = (const float*)d_in[15];
    const float* tf_b       = (const float*)d_in[16];
    const float* mlr_a      = (const float*)d_in[17];
    const float* mlr_p      = (const float*)d_in[18];
    float* out = (float*)d_out;

    float *attn2, *OFp, *FFp;
    __half *qkvh, *ah, *al, *wh;
    cudaGetSymbolAddress((void**)&qkvh,  g_qkvh);
    cudaGetSymbolAddress((void**)&attn2, g_attn2);
    cudaGetSymbolAddress((void**)&OFp,   g_OF);
    cudaGetSymbolAddress((void**)&FFp,   g_FF);
    cudaGetSymbolAddress((void**)&ah,    g_ah);
    cudaGetSymbolAddress((void**)&al,    g_al);
    cudaGetSymbolAddress((void**)&wh,    g_wh);

    cudaFuncSetAttribute(gemm_mma<float>, cudaFuncAttributeMaxDynamicSharedMemorySize, GEMM_DYN_SMEM);
    cudaFuncSetAttribute(gemm_mma<__half>, cudaFuncAttributeMaxDynamicSharedMemorySize, GEMM_DYN_SMEM);

    auto splitA = [&](const float* src, size_t n) {
        int n4 = (int)(n / 4);
        split_f16<<<(n4 + 255) / 256, 256>>>((const float4*)src, (uint2*)ah, (uint2*)al, n4);
    };
    auto convW = [&](const float* src, size_t n) {
        int n4 = (int)(n / 4);
        conv_f16<<<(n4 + 255) / 256, 256>>>((const float4*)src, (uint2*)wh, n4);
    };

    // 1. hyperbolic logmap + stack -> gf (+ fused fp16 hi/lo split of A)
    build_gf_kernel<<<BB, 256>>>(order_hyp, family_hyp, order_euc, family_euc);

    // 2. QKV GEMM: (16384,1024) x (3072,1024)^T -> fp16 qkv
    convW(in_proj_w, (size_t)3 * DD * DD);
    gemm_mma<__half><<<dim3((3 * DD) / TCBN, (BB * 4) / TCBM), 256, GEMM_DYN_SMEM>>>(
        ah, al, wh, in_proj_b, qkvh, BB * 4, 3 * DD, DD);

    // 3. attention (reads fp16 qkv, writes fp16 hi/lo A directly)
    attn_kernel<<<BB, 256>>>();

    // 4. out-proj GEMM (fp32 out)
    convW(out_proj_w, (size_t)DD * DD);
    gemm_mma<float><<<dim3(DD / TCBN, (BB * 4) / TCBM), 256, GEMM_DYN_SMEM>>>(
        ah, al, wh, out_proj_b, attn2, BB * 4, DD, DD);

    // 5. residual + LN + split + l_expmap0
    ln_split_kernel<<<BB * 4, 256>>>(ln_w, ln_b, out);

    // 6. feature GEMMs: (4096,768) x (1024,768)^T
    splitA(order_in, (size_t)BB * TT);
    convW(to_w, (size_t)DD * TT);
    gemm_mma<float><<<dim3(DD / TCBN, BB / TCBM), 256, GEMM_DYN_SMEM>>>(
        ah, al, wh, to_b, OFp, BB, DD, TT);
    splitA(family_in, (size_t)BB * TT);
    convW(tf_w, (size_t)DD * TT);
    gemm_mma<float><<<dim3(DD / TCBN, BB / TCBM), 256, GEMM_DYN_SMEM>>>(
        ah, al, wh, tf_b, FFp, BB, DD, TT);

    // 7-8. loss
    loss_kernel<<<BB, 256>>>(mask, out);
    loss_reduce_kernel<<<1, 1024>>>(mask, out);

    // 9-10. MLR logits
    mlr_prep_kernel<<<1, 512>>>(mlr_a, mlr_p);
    mlr_kernel<<<BB / MLRB, 512>>>(out);

    (void)in_sizes; (void)n_in; (void)out_size;
}